// round 10
// baseline (speedup 1.0000x reference)
#include <cuda_runtime.h>

// ---------------------------------------------------------------------------
// SlidingWindowAttention: x->QKV proj -> windowed attention -> out proj
// B=2, S=2048, H=16, hd=64, D=1024, window=512. All fp32.
// R6: double-buffered GEMMs (1 sync/tile, prefetch regs), double-buffered
//     K/V in attention, prescaled Q, full-block mask skip.
// ---------------------------------------------------------------------------

constexpr int BB  = 2;
constexpr int SS  = 2048;
constexpr int NH  = 16;
constexpr int HDm = 64;
constexpr int DM  = 1024;      // NH*HDm
constexpr int ND3 = 3072;      // 3*DM
constexpr int WIN = 512;
constexpr int MT  = BB * SS;   // 4096 rows

// Scratch (device globals: allocation-free)
__device__ float g_Q[BB * NH * SS * HDm];
__device__ float g_K[BB * NH * SS * HDm];
__device__ float g_V[BB * NH * SS * HDm];
__device__ float g_AO[BB * SS * DM];

// ---------------------------------------------------------------------------
// SGEMM: C[M=4096][N] = A[4096][1024] @ W[1024][N] + bias
// BM=BN=128, BK=8, 256 threads, 8x8 micro-tile, double-buffered smem.
// EPI==0: A = x param, scatter into g_Q/g_K/g_V (layout (b,h,s,d))
// EPI==1: A = g_AO, plain write to Cout + bias
// ---------------------------------------------------------------------------
template <int N, int EPI>
__global__ __launch_bounds__(256) void gemm_kernel(const float* __restrict__ A,
                                                   const float* __restrict__ Bmat,
                                                   const float* __restrict__ bias,
                                                   float* __restrict__ Cout)
{
    __shared__ float As[2][8][132];   // transposed A tile, padded
    __shared__ float Bs[2][8][128];

    const int tid = threadIdx.x;
    const int n0  = blockIdx.x * 128;
    const int m0  = blockIdx.y * 128;
    const int ty  = tid >> 4;          // 0..15 -> M rows ty*8..+7
    const int tx  = tid & 15;          // 0..15 -> N cols tx*8..+7
    const int arow = tid >> 1;         // 0..127
    const int acol = (tid & 1) * 4;    // 0 or 4
    const int brow = tid >> 5;         // 0..7
    const int bcol = (tid & 31) * 4;   // 0..124

    const float* Ap = (EPI == 0) ? A : g_AO;

    float acc[8][8];
#pragma unroll
    for (int i = 0; i < 8; i++)
#pragma unroll
        for (int j = 0; j < 8; j++) acc[i][j] = 0.f;

    const float* aptr = Ap + (m0 + arow) * DM + acol;
    const float* bptr = Bmat + brow * N + n0 + bcol;

    // Prologue: fill buffer 0
    {
        float4 a4 = *(const float4*)(aptr);
        float4 b4 = *(const float4*)(bptr);
        As[0][acol + 0][arow] = a4.x;
        As[0][acol + 1][arow] = a4.y;
        As[0][acol + 2][arow] = a4.z;
        As[0][acol + 3][arow] = a4.w;
        *(float4*)&Bs[0][brow][bcol] = b4;
    }
    __syncthreads();

    int buf = 0;
    for (int k0 = 8; k0 < DM; k0 += 8) {
        // Prefetch next tile into registers (latency hidden by compute below)
        float4 an = *(const float4*)(aptr + k0);
        float4 bn = *(const float4*)(bptr + k0 * N);

#pragma unroll
        for (int k = 0; k < 8; k++) {
            float af[8], bf[8];
            *(float4*)&af[0] = *(const float4*)&As[buf][k][ty * 8];
            *(float4*)&af[4] = *(const float4*)&As[buf][k][ty * 8 + 4];
            *(float4*)&bf[0] = *(const float4*)&Bs[buf][k][tx * 8];
            *(float4*)&bf[4] = *(const float4*)&Bs[buf][k][tx * 8 + 4];
#pragma unroll
            for (int i = 0; i < 8; i++)
#pragma unroll
                for (int j = 0; j < 8; j++)
                    acc[i][j] = fmaf(af[i], bf[j], acc[i][j]);
        }

        const int nb = buf ^ 1;
        As[nb][acol + 0][arow] = an.x;
        As[nb][acol + 1][arow] = an.y;
        As[nb][acol + 2][arow] = an.z;
        As[nb][acol + 3][arow] = an.w;
        *(float4*)&Bs[nb][brow][bcol] = bn;
        __syncthreads();
        buf = nb;
    }

    // Final tile compute
#pragma unroll
    for (int k = 0; k < 8; k++) {
        float af[8], bf[8];
        *(float4*)&af[0] = *(const float4*)&As[buf][k][ty * 8];
        *(float4*)&af[4] = *(const float4*)&As[buf][k][ty * 8 + 4];
        *(float4*)&bf[0] = *(const float4*)&Bs[buf][k][tx * 8];
        *(float4*)&bf[4] = *(const float4*)&Bs[buf][k][tx * 8 + 4];
#pragma unroll
        for (int i = 0; i < 8; i++)
#pragma unroll
            for (int j = 0; j < 8; j++)
                acc[i][j] = fmaf(af[i], bf[j], acc[i][j]);
    }

    if (EPI == 0) {
        // n0 multiple of 128, 1024%128==0 -> 'which' uniform per CTA
        const int which = n0 >> 10;
        float* dst = (which == 0) ? g_Q : (which == 1) ? g_K : g_V;
        const int n_base = n0 + tx * 8;       // stays inside one head
        const int rem = n_base & (DM - 1);
        const int hh  = rem >> 6;
        const int d0  = rem & 63;
#pragma unroll
        for (int i = 0; i < 8; i++) {
            const int m  = m0 + ty * 8 + i;
            const int bb = m >> 11;           // /SS
            const int ss = m & (SS - 1);
            float* row = dst + ((bb * NH + hh) * SS + ss) * HDm + d0;
#pragma unroll
            for (int j = 0; j < 8; j++)
                row[j] = acc[i][j] + bias[n_base + j];
        }
    } else {
        const int n_base = n0 + tx * 8;
        float bv[8];
#pragma unroll
        for (int j = 0; j < 8; j++) bv[j] = bias[n_base + j];
#pragma unroll
        for (int i = 0; i < 8; i++) {
            const int m = m0 + ty * 8 + i;
            float4 v0, v1;
            v0.x = acc[i][0] + bv[0]; v0.y = acc[i][1] + bv[1];
            v0.z = acc[i][2] + bv[2]; v0.w = acc[i][3] + bv[3];
            v1.x = acc[i][4] + bv[4]; v1.y = acc[i][5] + bv[5];
            v1.z = acc[i][6] + bv[6]; v1.w = acc[i][7] + bv[7];
            *(float4*)&Cout[m * N + n_base]     = v0;
            *(float4*)&Cout[m * N + n_base + 4] = v1;
        }
    }
}

// ---------------------------------------------------------------------------
// Windowed flash attention. One CTA per (64-query tile, head, batch).
// 256 threads = 16x16; each thread owns 4q x 4col.
// Double-buffered K/V; Q prescaled by 1/8.
// Smem: Qst | Kst0 | Vs0 | Kst1 | Vs1 | Pst (each 64 x PITCH floats)
// ---------------------------------------------------------------------------
constexpr int PITCH = 68;
constexpr int TSZ = 64 * PITCH;
constexpr int ATTN_SMEM_BYTES = 6 * TSZ * (int)sizeof(float);  // 104448

__device__ __forceinline__ void load_kv(const float* __restrict__ Kb,
                                        const float* __restrict__ Vb,
                                        float* __restrict__ Kst,
                                        float* __restrict__ Vs,
                                        int tid)
{
#pragma unroll
    for (int it = 0; it < 4; it++) {
        const int t = tid + it * 256;
        const int r = t >> 4;
        const int c = (t & 15) * 4;
        float4 kv = *(const float4*)(Kb + r * HDm + c);
        Kst[(c + 0) * PITCH + r] = kv.x;
        Kst[(c + 1) * PITCH + r] = kv.y;
        Kst[(c + 2) * PITCH + r] = kv.z;
        Kst[(c + 3) * PITCH + r] = kv.w;
        float4 vv = *(const float4*)(Vb + r * HDm + c);
        *(float4*)&Vs[r * PITCH + c] = vv;
    }
}

__global__ __launch_bounds__(256) void attn_kernel()
{
    extern __shared__ float smf[];
    float* Qst = smf;                       // [kd][q]
    float* Pst = smf + 5 * TSZ;             // [k][q]

    const int tid = threadIdx.x;
    const int ty  = tid >> 4;     // rows ty*4..+3
    const int tx  = tid & 15;     // cols tx*4..+3
    const int q0  = blockIdx.x * 64;
    const int h   = blockIdx.y;
    const int b   = blockIdx.z;

    const float* Qg = g_Q + (size_t)(b * NH + h) * SS * HDm;
    const float* Kg = g_K + (size_t)(b * NH + h) * SS * HDm;
    const float* Vg = g_V + (size_t)(b * NH + h) * SS * HDm;

    // Load Q tile (64 x 64) transposed to kd-major, prescaled by 1/sqrt(hd)
#pragma unroll
    for (int it = 0; it < 4; it++) {
        const int t = tid + it * 256;
        const int r = t >> 4;
        const int c = (t & 15) * 4;
        float4 v = *(const float4*)(Qg + (q0 + r) * HDm + c);
        Qst[(c + 0) * PITCH + r] = v.x * 0.125f;
        Qst[(c + 1) * PITCH + r] = v.y * 0.125f;
        Qst[(c + 2) * PITCH + r] = v.z * 0.125f;
        Qst[(c + 3) * PITCH + r] = v.w * 0.125f;
    }

    float m_prev[4], lsum[4], o[4][4];
#pragma unroll
    for (int i = 0; i < 4; i++) {
        m_prev[i] = -1e30f;
        lsum[i] = 0.f;
#pragma unroll
        for (int j = 0; j < 4; j++) o[i][j] = 0.f;
    }

    const int kb_start = (q0 >= WIN) ? ((q0 - (WIN - 1)) >> 6) : 0;
    const int kb_end   = q0 >> 6;    // inclusive

    // Prologue: fill buffer 0 with first K/V block
    load_kv(Kg + kb_start * 64 * HDm, Vg + kb_start * 64 * HDm,
            smf + 1 * TSZ, smf + 2 * TSZ, tid);
    __syncthreads();

    int buf = 0;
    for (int kb = kb_start; kb <= kb_end; kb++) {
        float* Kst = smf + (1 + 2 * buf) * TSZ;
        float* Vs  = Kst + TSZ;

        // Prefetch next K/V block into the other buffer (consumed next iter)
        if (kb < kb_end) {
            float* Kn = smf + (1 + 2 * (buf ^ 1)) * TSZ;
            load_kv(Kg + (kb + 1) * 64 * HDm, Vg + (kb + 1) * 64 * HDm,
                    Kn, Kn + TSZ, tid);
        }

        // S = Q @ K^T (per-thread 4x4), scale already folded into Q
        float sacc[4][4];
#pragma unroll
        for (int i = 0; i < 4; i++)
#pragma unroll
            for (int j = 0; j < 4; j++) sacc[i][j] = 0.f;

#pragma unroll 16
        for (int kd = 0; kd < 64; kd++) {
            float4 qf = *(const float4*)&Qst[kd * PITCH + ty * 4];
            float4 kf = *(const float4*)&Kst[kd * PITCH + tx * 4];
            const float qa[4] = {qf.x, qf.y, qf.z, qf.w};
            const float ka[4] = {kf.x, kf.y, kf.z, kf.w};
#pragma unroll
            for (int i = 0; i < 4; i++)
#pragma unroll
                for (int j = 0; j < 4; j++)
                    sacc[i][j] = fmaf(qa[i], ka[j], sacc[i][j]);
        }

        // Is this key block fully inside the window for every (q, j) pair?
        const int diff = q0 - kb * 64;
        const bool full = (diff >= 63) && (diff + 63 < WIN);

        // Online softmax (rows distributed over 16-lane groups)
#pragma unroll
        for (int i = 0; i < 4; i++) {
            float sv[4];
            float rowmax = -1e30f;
            if (full) {
#pragma unroll
                for (int j = 0; j < 4; j++) {
                    sv[j] = sacc[i][j];
                    rowmax = fmaxf(rowmax, sv[j]);
                }
            } else {
                const int qg = q0 + ty * 4 + i;
#pragma unroll
                for (int j = 0; j < 4; j++) {
                    const int jg = kb * 64 + tx * 4 + j;
                    const int d  = qg - jg;
                    const bool valid = (d >= 0) && (d < WIN);
                    sv[j] = valid ? sacc[i][j] : -1e30f;
                    rowmax = fmaxf(rowmax, sv[j]);
                }
            }
#pragma unroll
            for (int off = 8; off > 0; off >>= 1)
                rowmax = fmaxf(rowmax, __shfl_xor_sync(0xffffffffu, rowmax, off));
            const float mn = fmaxf(m_prev[i], rowmax);
            float psum = 0.f;
#pragma unroll
            for (int j = 0; j < 4; j++) {
                const float p = (sv[j] > -1e29f) ? __expf(sv[j] - mn) : 0.f;
                psum += p;
                Pst[(tx * 4 + j) * PITCH + ty * 4 + i] = p;   // k-major
            }
#pragma unroll
            for (int off = 8; off > 0; off >>= 1)
                psum += __shfl_xor_sync(0xffffffffu, psum, off);
            const float corr = __expf(m_prev[i] - mn);  // 0 on first block
            lsum[i] = lsum[i] * corr + psum;
            m_prev[i] = mn;
#pragma unroll
            for (int j = 0; j < 4; j++) o[i][j] *= corr;
        }
        __syncthreads();

        // O += P @ V
#pragma unroll 16
        for (int k = 0; k < 64; k++) {
            float4 pf = *(const float4*)&Pst[k * PITCH + ty * 4];
            float4 vf = *(const float4*)&Vs[k * PITCH + tx * 4];
            const float pa[4] = {pf.x, pf.y, pf.z, pf.w};
            const float va[4] = {vf.x, vf.y, vf.z, vf.w};
#pragma unroll
            for (int i = 0; i < 4; i++)
#pragma unroll
                for (int j = 0; j < 4; j++)
                    o[i][j] = fmaf(pa[i], va[j], o[i][j]);
        }
        __syncthreads();
        buf ^= 1;
    }

    // Normalize + store to attention scratch in (b, s, h*hd) layout
#pragma unroll
    for (int i = 0; i < 4; i++) {
        const int qg = q0 + ty * 4 + i;
        const float inv = 1.f / lsum[i];
        float4 v;
        v.x = o[i][0] * inv; v.y = o[i][1] * inv;
        v.z = o[i][2] * inv; v.w = o[i][3] * inv;
        *(float4*)&g_AO[(size_t)(b * SS + qg) * DM + h * HDm + tx * 4] = v;
    }
}

// ---------------------------------------------------------------------------
extern "C" void kernel_launch(void* const* d_in, const int* in_sizes, int n_in,
                              void* d_out, int out_size)
{
    const float* x     = (const float*)d_in[0];
    const float* qkvw  = (const float*)d_in[1];
    const float* qkvb  = (const float*)d_in[2];
    const float* outw  = (const float*)d_in[3];
    const float* outb  = (const float*)d_in[4];
    float* out = (float*)d_out;

    cudaFuncSetAttribute(attn_kernel, cudaFuncAttributeMaxDynamicSharedMemorySize,
                         ATTN_SMEM_BYTES);

    // 1) QKV projection (scatter into Q/K/V scratch)
    gemm_kernel<ND3, 0><<<dim3(ND3 / 128, MT / 128), 256>>>(x, qkvw, qkvb, nullptr);

    // 2) Windowed attention
    attn_kernel<<<dim3(SS / 64, NH, BB), 256, ATTN_SMEM_BYTES>>>();

    // 3) Output projection
    gemm_kernel<DM, 1><<<dim3(DM / 128, MT / 128), 256>>>(nullptr, outw, outb, out);
}

// round 12
// speedup vs baseline: 1.3952x; 1.3952x over previous
#include <cuda_runtime.h>
#include <cuda_bf16.h>
#include <cstdint>

// ---------------------------------------------------------------------------
// SlidingWindowAttention on GB300 (sm_103 base target — NO tcgen05 available)
// R11: split-precision (3xBF16 K-concat) GEMMs on mma.sync.m16n8k16 HMMA.
//      fp32 flash attention unchanged; attention epilogue emits split bf16.
// ---------------------------------------------------------------------------

constexpr int BB  = 2;
constexpr int SS  = 2048;
constexpr int NH  = 16;
constexpr int HDm = 64;
constexpr int DM  = 1024;      // NH*HDm
constexpr int ND3 = 3072;      // 3*DM
constexpr int WIN = 512;
constexpr int MT  = BB * SS;   // 4096 rows
constexpr int KCAT = 3 * DM;   // 3072 (hi|hi-lo concat K)

// Scratch (device globals: allocation-free)
__device__ float g_Q[BB * NH * SS * HDm];
__device__ float g_K[BB * NH * SS * HDm];
__device__ float g_V[BB * NH * SS * HDm];
__device__ __nv_bfloat16 g_Acat [MT * KCAT];    // [x_hi | x_hi | x_lo]
__device__ __nv_bfloat16 g_AOcat[MT * KCAT];    // attention out, same split
__device__ __nv_bfloat16 g_Bq[ND3 * KCAT];      // qkv weights^T [w_hi|w_lo|w_hi]
__device__ __nv_bfloat16 g_Bo[DM  * KCAT];      // out  weights^T

// ============================= MMA helpers =================================
#define LDSM_X4(R, addr)                                                      \
    asm volatile("ldmatrix.sync.aligned.m8n8.x4.shared.b16 {%0,%1,%2,%3}, [%4];" \
        : "=r"((R)[0]), "=r"((R)[1]), "=r"((R)[2]), "=r"((R)[3]) : "r"(addr))

#define MMA16816(C, A, b0, b1)                                                \
    asm volatile("mma.sync.aligned.m16n8k16.row.col.f32.bf16.bf16.f32 "       \
        "{%0,%1,%2,%3},{%4,%5,%6,%7},{%8,%9},{%0,%1,%2,%3};"                  \
        : "+f"((C)[0]), "+f"((C)[1]), "+f"((C)[2]), "+f"((C)[3])              \
        : "r"((A)[0]), "r"((A)[1]), "r"((A)[2]), "r"((A)[3]), "r"(b0), "r"(b1))

__device__ __forceinline__ uint32_t smem_u32(const void* p) {
    uint32_t a;
    asm("{ .reg .u64 t; cvta.to.shared.u64 t, %1; cvt.u32.u64 %0, t; }"
        : "=r"(a) : "l"(p));
    return a;
}

// ============================ split helpers ================================
__device__ __forceinline__ void split_bf16(float x, __nv_bfloat16& hi, __nv_bfloat16& lo) {
    hi = __float2bfloat16_rn(x);
    lo = __float2bfloat16_rn(x - __bfloat162float(hi));
}

// ========================= conversion kernels ==============================
// x (MT x DM f32) -> A_cat (MT x 3072 bf16) = [hi | hi | lo]
__global__ __launch_bounds__(256) void conv_x(const float* __restrict__ X,
                                              __nv_bfloat16* __restrict__ A)
{
    const int idx = blockIdx.x * 256 + threadIdx.x;   // float4 index
    const int m  = idx >> 8;            // DM/4 = 256 float4 per row
    const int c  = (idx & 255) * 4;
    float4 v = *(const float4*)(X + m * DM + c);
    __nv_bfloat16 h[4], l[4];
    split_bf16(v.x, h[0], l[0]); split_bf16(v.y, h[1], l[1]);
    split_bf16(v.z, h[2], l[2]); split_bf16(v.w, h[3], l[3]);
    __nv_bfloat162 h01, h23, l01, l23;
    h01.x = h[0]; h01.y = h[1]; h23.x = h[2]; h23.y = h[3];
    l01.x = l[0]; l01.y = l[1]; l23.x = l[2]; l23.y = l[3];
    __nv_bfloat16* row = A + (size_t)m * KCAT;
    *(__nv_bfloat162*)(row + c)            = h01;
    *(__nv_bfloat162*)(row + c + 2)        = h23;
    *(__nv_bfloat162*)(row + DM + c)       = h01;
    *(__nv_bfloat162*)(row + DM + c + 2)   = h23;
    *(__nv_bfloat162*)(row + 2*DM + c)     = l01;
    *(__nv_bfloat162*)(row + 2*DM + c + 2) = l23;
}

// W (DM x Nn f32, row-major) -> Bcat (Nn x 3072 bf16) = [w_hi | w_lo | w_hi]
__global__ __launch_bounds__(256) void conv_w(const float* __restrict__ W,
                                              __nv_bfloat16* __restrict__ Bc,
                                              int Nn)
{
    __shared__ float t[32][33];
    const int tx = threadIdx.x, ty = threadIdx.y;
    const int n0 = blockIdx.x * 32, k0 = blockIdx.y * 32;
#pragma unroll
    for (int i = 0; i < 32; i += 8)
        t[ty + i][tx] = W[(size_t)(k0 + ty + i) * Nn + n0 + tx];
    __syncthreads();
#pragma unroll
    for (int i = 0; i < 32; i += 8) {
        const int n = n0 + ty + i;
        const float v = t[tx][ty + i];
        __nv_bfloat16 hi, lo;
        split_bf16(v, hi, lo);
        __nv_bfloat16* row = Bc + (size_t)n * KCAT + k0 + tx;
        row[0]      = hi;
        row[DM]     = lo;
        row[2 * DM] = hi;
    }
}

// ======================= HMMA bf16 GEMM ====================================
// C[M=4096][N] = A_cat[M][3072] @ B_cat[N][3072]^T + bias
// 128x128 CTA tile, 8 warps (4m x 2n), each warp 32x64.
// BK=32 chunks, double-buffered smem (80B row pitch), register prefetch.
// EPI==0: scatter to g_Q/g_K/g_V (b,h,s,d).  EPI==1: row-major to Cout.
constexpr int PIT = 80;                 // bytes per 32-bf16 row (64B + 16B pad)
constexpr int NCH = KCAT / 32;          // 96 chunks

template <int EPI>
__global__ __launch_bounds__(256) void tgemm(const __nv_bfloat16* __restrict__ Acat,
                                             const __nv_bfloat16* __restrict__ Bcat,
                                             const float* __restrict__ bias,
                                             float* __restrict__ Cout)
{
    __shared__ __align__(16) char smA[2][128 * PIT];
    __shared__ __align__(16) char smB[2][128 * PIT];

    const int tid  = threadIdx.x;
    const int wid  = tid >> 5;
    const int lane = tid & 31;
    const int wm   = wid >> 1;          // 0..3 -> rows wm*32
    const int wn   = wid & 1;           // 0..1 -> cols wn*64
    const int n0   = blockIdx.x * 128;
    const int m0   = blockIdx.y * 128;

    const __nv_bfloat16* gA = Acat + (size_t)m0 * KCAT;
    const __nv_bfloat16* gB = Bcat + (size_t)n0 * KCAT;

    // staging indices for global->smem (512 x 16B chunks per operand per stage)
    const int ldRow0 = tid >> 2;            // rows tid/4 and +64
    const int ldCC   = (tid & 3) * 16;      // byte col within 64B row

    // ldmatrix lane addresses (byte offsets within a stage)
    // A: x4 tile rows r0+ (lane&15), k-half (lane>>4)*16B
    const int aOff0 = (wm * 32 +      (lane & 15)) * PIT + (lane >> 4) * 16;
    const int aOff1 = (wm * 32 + 16 + (lane & 15)) * PIT + (lane >> 4) * 16;
    // B: x4 covers 16 n-rows x k16: rows n0w + (lane&7) + ((lane>>4)<<3),
    //    k-half ((lane>>3)&1)*16B
    const int bRow = wn * 64 + (lane & 7) + ((lane >> 4) << 3);
    const int bCol = ((lane >> 3) & 1) * 16;
    int bOff[4];
#pragma unroll
    for (int bt = 0; bt < 4; bt++)
        bOff[bt] = (bRow + bt * 16) * PIT + bCol;

    const uint32_t sA0 = smem_u32(smA[0]);
    const uint32_t sA1 = smem_u32(smA[1]);
    const uint32_t sB0 = smem_u32(smB[0]);
    const uint32_t sB1 = smem_u32(smB[1]);

    float c[2][8][4];
#pragma unroll
    for (int mt = 0; mt < 2; mt++)
#pragma unroll
        for (int nt = 0; nt < 8; nt++)
#pragma unroll
            for (int r = 0; r < 4; r++) c[mt][nt][r] = 0.f;

    // ---- load chunk 0 into stage 0
    {
        const char* pa0 = (const char*)(gA + (size_t)ldRow0 * KCAT);
        const char* pa1 = (const char*)(gA + (size_t)(ldRow0 + 64) * KCAT);
        const char* pb0 = (const char*)(gB + (size_t)ldRow0 * KCAT);
        const char* pb1 = (const char*)(gB + (size_t)(ldRow0 + 64) * KCAT);
        *(uint4*)(smA[0] + ldRow0 * PIT + ldCC)        = *(const uint4*)(pa0 + ldCC);
        *(uint4*)(smA[0] + (ldRow0 + 64) * PIT + ldCC) = *(const uint4*)(pa1 + ldCC);
        *(uint4*)(smB[0] + ldRow0 * PIT + ldCC)        = *(const uint4*)(pb0 + ldCC);
        *(uint4*)(smB[0] + (ldRow0 + 64) * PIT + ldCC) = *(const uint4*)(pb1 + ldCC);
    }
    __syncthreads();

    int buf = 0;
    for (int ch = 1; ch <= NCH; ch++) {
        // prefetch next chunk into registers
        uint4 pfa0, pfa1, pfb0, pfb1;
        if (ch < NCH) {
            const size_t kb = (size_t)ch * 64;   // byte offset of chunk in K
            pfa0 = *(const uint4*)((const char*)(gA + (size_t)ldRow0 * KCAT) + kb + ldCC);
            pfa1 = *(const uint4*)((const char*)(gA + (size_t)(ldRow0 + 64) * KCAT) + kb + ldCC);
            pfb0 = *(const uint4*)((const char*)(gB + (size_t)ldRow0 * KCAT) + kb + ldCC);
            pfb1 = *(const uint4*)((const char*)(gB + (size_t)(ldRow0 + 64) * KCAT) + kb + ldCC);
        }

        // compute on current stage
        const uint32_t baseA = buf ? sA1 : sA0;
        const uint32_t baseB = buf ? sB1 : sB0;
#pragma unroll
        for (int ks = 0; ks < 2; ks++) {
            const int ko = ks * 32;   // 16 bf16 = 32 bytes
            uint32_t a[2][4];
            LDSM_X4(a[0], baseA + aOff0 + ko);
            LDSM_X4(a[1], baseA + aOff1 + ko);
            uint32_t bf[4][4];
#pragma unroll
            for (int bt = 0; bt < 4; bt++)
                LDSM_X4(bf[bt], baseB + bOff[bt] + ko);
#pragma unroll
            for (int mt = 0; mt < 2; mt++)
#pragma unroll
                for (int nt = 0; nt < 8; nt++) {
                    const uint32_t b0 = bf[nt >> 1][(nt & 1) * 2 + 0];
                    const uint32_t b1 = bf[nt >> 1][(nt & 1) * 2 + 1];
                    MMA16816(c[mt][nt], a[mt], b0, b1);
                }
        }

        if (ch < NCH) {
            char* dA = smA[buf ^ 1];
            char* dB = smB[buf ^ 1];
            *(uint4*)(dA + ldRow0 * PIT + ldCC)        = pfa0;
            *(uint4*)(dA + (ldRow0 + 64) * PIT + ldCC) = pfa1;
            *(uint4*)(dB + ldRow0 * PIT + ldCC)        = pfb0;
            *(uint4*)(dB + (ldRow0 + 64) * PIT + ldCC) = pfb1;
            __syncthreads();
            buf ^= 1;
        }
    }

    // ---- epilogue ----
    const int g  = lane >> 2;       // 0..7
    const int tg = lane & 3;        // 0..3
#pragma unroll
    for (int mt = 0; mt < 2; mt++) {
#pragma unroll
        for (int half = 0; half < 2; half++) {     // row g / g+8
            const int m = m0 + wm * 32 + mt * 16 + g + half * 8;
            if (EPI == 0) {
                const int which = n0 >> 10;        // uniform per CTA
                float* dst = (which == 0) ? g_Q : (which == 1) ? g_K : g_V;
                const int bb = m >> 11;
                const int ss = m & (SS - 1);
#pragma unroll
                for (int nt = 0; nt < 8; nt++) {
                    const int n = n0 + wn * 64 + nt * 8 + tg * 2;
                    const int hh = (n & (DM - 1)) >> 6;
                    const int d0 = n & 63;
                    float2 v;
                    v.x = c[mt][nt][half * 2 + 0] + bias[n + 0];
                    v.y = c[mt][nt][half * 2 + 1] + bias[n + 1];
                    *(float2*)(dst + ((size_t)(bb * NH + hh) * SS + ss) * HDm + d0) = v;
                }
            } else {
#pragma unroll
                for (int nt = 0; nt < 8; nt++) {
                    const int n = n0 + wn * 64 + nt * 8 + tg * 2;
                    float2 v;
                    v.x = c[mt][nt][half * 2 + 0] + bias[n + 0];
                    v.y = c[mt][nt][half * 2 + 1] + bias[n + 1];
                    *(float2*)(Cout + (size_t)m * DM + n) = v;
                }
            }
        }
    }
}

// ---------------------------------------------------------------------------
// Windowed flash attention (fp32). Epilogue writes split-bf16 into g_AOcat.
// ---------------------------------------------------------------------------
constexpr int PITCH = 68;
constexpr int TSZ = 64 * PITCH;
constexpr int ATTN_SMEM_BYTES = 6 * TSZ * (int)sizeof(float);  // 104448

__device__ __forceinline__ void load_kv(const float* __restrict__ Kb,
                                        const float* __restrict__ Vb,
                                        float* __restrict__ Kst,
                                        float* __restrict__ Vs,
                                        int tid)
{
#pragma unroll
    for (int it = 0; it < 4; it++) {
        const int t = tid + it * 256;
        const int r = t >> 4;
        const int c = (t & 15) * 4;
        float4 kv = *(const float4*)(Kb + r * HDm + c);
        Kst[(c + 0) * PITCH + r] = kv.x;
        Kst[(c + 1) * PITCH + r] = kv.y;
        Kst[(c + 2) * PITCH + r] = kv.z;
        Kst[(c + 3) * PITCH + r] = kv.w;
        float4 vv = *(const float4*)(Vb + r * HDm + c);
        *(float4*)&Vs[r * PITCH + c] = vv;
    }
}

__global__ __launch_bounds__(256) void attn_kernel()
{
    extern __shared__ float smf[];
    float* Qst = smf;
    float* Pst = smf + 5 * TSZ;

    const int tid = threadIdx.x;
    const int ty  = tid >> 4;
    const int tx  = tid & 15;
    const int q0  = blockIdx.x * 64;
    const int h   = blockIdx.y;
    const int b   = blockIdx.z;

    const float* Qg = g_Q + (size_t)(b * NH + h) * SS * HDm;
    const float* Kg = g_K + (size_t)(b * NH + h) * SS * HDm;
    const float* Vg = g_V + (size_t)(b * NH + h) * SS * HDm;

#pragma unroll
    for (int it = 0; it < 4; it++) {
        const int t = tid + it * 256;
        const int r = t >> 4;
        const int c = (t & 15) * 4;
        float4 v = *(const float4*)(Qg + (q0 + r) * HDm + c);
        Qst[(c + 0) * PITCH + r] = v.x * 0.125f;
        Qst[(c + 1) * PITCH + r] = v.y * 0.125f;
        Qst[(c + 2) * PITCH + r] = v.z * 0.125f;
        Qst[(c + 3) * PITCH + r] = v.w * 0.125f;
    }

    float m_prev[4], lsum[4], o[4][4];
#pragma unroll
    for (int i = 0; i < 4; i++) {
        m_prev[i] = -1e30f;
        lsum[i] = 0.f;
#pragma unroll
        for (int j = 0; j < 4; j++) o[i][j] = 0.f;
    }

    const int kb_start = (q0 >= WIN) ? ((q0 - (WIN - 1)) >> 6) : 0;
    const int kb_end   = q0 >> 6;

    load_kv(Kg + kb_start * 64 * HDm, Vg + kb_start * 64 * HDm,
            smf + 1 * TSZ, smf + 2 * TSZ, tid);
    __syncthreads();

    int buf = 0;
    for (int kb = kb_start; kb <= kb_end; kb++) {
        float* Kst = smf + (1 + 2 * buf) * TSZ;
        float* Vs  = Kst + TSZ;

        if (kb < kb_end) {
            float* Kn = smf + (1 + 2 * (buf ^ 1)) * TSZ;
            load_kv(Kg + (kb + 1) * 64 * HDm, Vg + (kb + 1) * 64 * HDm,
                    Kn, Kn + TSZ, tid);
        }

        float sacc[4][4];
#pragma unroll
        for (int i = 0; i < 4; i++)
#pragma unroll
            for (int j = 0; j < 4; j++) sacc[i][j] = 0.f;

#pragma unroll 16
        for (int kd = 0; kd < 64; kd++) {
            float4 qf = *(const float4*)&Qst[kd * PITCH + ty * 4];
            float4 kf = *(const float4*)&Kst[kd * PITCH + tx * 4];
            const float qa[4] = {qf.x, qf.y, qf.z, qf.w};
            const float ka[4] = {kf.x, kf.y, kf.z, kf.w};
#pragma unroll
            for (int i = 0; i < 4; i++)
#pragma unroll
                for (int j = 0; j < 4; j++)
                    sacc[i][j] = fmaf(qa[i], ka[j], sacc[i][j]);
        }

        const int diff = q0 - kb * 64;
        const bool full = (diff >= 63) && (diff + 63 < WIN);

#pragma unroll
        for (int i = 0; i < 4; i++) {
            float sv[4];
            float rowmax = -1e30f;
            if (full) {
#pragma unroll
                for (int j = 0; j < 4; j++) {
                    sv[j] = sacc[i][j];
                    rowmax = fmaxf(rowmax, sv[j]);
                }
            } else {
                const int qg = q0 + ty * 4 + i;
#pragma unroll
                for (int j = 0; j < 4; j++) {
                    const int jg = kb * 64 + tx * 4 + j;
                    const int d  = qg - jg;
                    const bool valid = (d >= 0) && (d < WIN);
                    sv[j] = valid ? sacc[i][j] : -1e30f;
                    rowmax = fmaxf(rowmax, sv[j]);
                }
            }
#pragma unroll
            for (int off = 8; off > 0; off >>= 1)
                rowmax = fmaxf(rowmax, __shfl_xor_sync(0xffffffffu, rowmax, off));
            const float mn = fmaxf(m_prev[i], rowmax);
            float psum = 0.f;
#pragma unroll
            for (int j = 0; j < 4; j++) {
                const float p = (sv[j] > -1e29f) ? __expf(sv[j] - mn) : 0.f;
                psum += p;
                Pst[(tx * 4 + j) * PITCH + ty * 4 + i] = p;
            }
#pragma unroll
            for (int off = 8; off > 0; off >>= 1)
                psum += __shfl_xor_sync(0xffffffffu, psum, off);
            const float corr = __expf(m_prev[i] - mn);
            lsum[i] = lsum[i] * corr + psum;
            m_prev[i] = mn;
#pragma unroll
            for (int j = 0; j < 4; j++) o[i][j] *= corr;
        }
        __syncthreads();

#pragma unroll 16
        for (int k = 0; k < 64; k++) {
            float4 pf = *(const float4*)&Pst[k * PITCH + ty * 4];
            float4 vf = *(const float4*)&Vs[k * PITCH + tx * 4];
            const float pa[4] = {pf.x, pf.y, pf.z, pf.w};
            const float va[4] = {vf.x, vf.y, vf.z, vf.w};
#pragma unroll
            for (int i = 0; i < 4; i++)
#pragma unroll
                for (int j = 0; j < 4; j++)
                    o[i][j] = fmaf(pa[i], va[j], o[i][j]);
        }
        __syncthreads();
        buf ^= 1;
    }

    // epilogue: normalize, split to bf16 hi/lo, write A_cat layout [hi|hi|lo]
#pragma unroll
    for (int i = 0; i < 4; i++) {
        const int qg = q0 + ty * 4 + i;
        const float inv = 1.f / lsum[i];
        float v[4];
#pragma unroll
        for (int j = 0; j < 4; j++) v[j] = o[i][j] * inv;
        __nv_bfloat16 h4[4], l4[4];
#pragma unroll
        for (int j = 0; j < 4; j++) split_bf16(v[j], h4[j], l4[j]);
        __nv_bfloat162 h01, h23, l01, l23;
        h01.x = h4[0]; h01.y = h4[1]; h23.x = h4[2]; h23.y = h4[3];
        l01.x = l4[0]; l01.y = l4[1]; l23.x = l4[2]; l23.y = l4[3];
        __nv_bfloat16* row = g_AOcat + (size_t)(b * SS + qg) * KCAT + h * HDm + tx * 4;
        *(__nv_bfloat162*)(row)              = h01;
        *(__nv_bfloat162*)(row + 2)          = h23;
        *(__nv_bfloat162*)(row + DM)         = h01;
        *(__nv_bfloat162*)(row + DM + 2)     = h23;
        *(__nv_bfloat162*)(row + 2*DM)       = l01;
        *(__nv_bfloat162*)(row + 2*DM + 2)   = l23;
    }
}

// ---------------------------------------------------------------------------
extern "C" void kernel_launch(void* const* d_in, const int* in_sizes, int n_in,
                              void* d_out, int out_size)
{
    const float* x     = (const float*)d_in[0];
    const float* qkvw  = (const float*)d_in[1];
    const float* qkvb  = (const float*)d_in[2];
    const float* outw  = (const float*)d_in[3];
    const float* outb  = (const float*)d_in[4];
    float* out = (float*)d_out;

    cudaFuncSetAttribute(attn_kernel, cudaFuncAttributeMaxDynamicSharedMemorySize,
                         ATTN_SMEM_BYTES);

    __nv_bfloat16 *Acat, *AOcat, *Bq, *Bo;
    cudaGetSymbolAddress((void**)&Acat,  g_Acat);
    cudaGetSymbolAddress((void**)&AOcat, g_AOcat);
    cudaGetSymbolAddress((void**)&Bq,    g_Bq);
    cudaGetSymbolAddress((void**)&Bo,    g_Bo);

    // 0) split-precision conversions
    conv_x<<<MT * DM / 1024, 256>>>(x, Acat);
    conv_w<<<dim3(ND3 / 32, DM / 32), dim3(32, 8)>>>(qkvw, Bq, ND3);
    conv_w<<<dim3(DM  / 32, DM / 32), dim3(32, 8)>>>(outw, Bo, DM);

    // 1) QKV projection (bf16 HMMA, scatter to Q/K/V)
    tgemm<0><<<dim3(ND3 / 128, MT / 128), 256>>>(Acat, Bq, qkvb, nullptr);

    // 2) Windowed attention (fp32), writes split-bf16 AO
    attn_kernel<<<dim3(SS / 64, NH, BB), 256, ATTN_SMEM_BYTES>>>();

    // 3) Output projection (bf16 HMMA)
    tgemm<1><<<dim3(DM / 128, MT / 128), 256>>>(AOcat, Bo, outb, out);
}

// round 13
// speedup vs baseline: 1.5288x; 1.0957x over previous
#include <cuda_runtime.h>
#include <cuda_bf16.h>
#include <cstdint>

// ---------------------------------------------------------------------------
// SlidingWindowAttention on GB300 (sm_103 base target — no tcgen05)
// R12: split-precision bf16 HMMA GEMMs, now with 3-stage cp.async pipeline
//      and 2 CTAs/SM (reg cap 128). fp32 flash attention unchanged.
// ---------------------------------------------------------------------------

constexpr int BB  = 2;
constexpr int SS  = 2048;
constexpr int NH  = 16;
constexpr int HDm = 64;
constexpr int DM  = 1024;      // NH*HDm
constexpr int ND3 = 3072;      // 3*DM
constexpr int WIN = 512;
constexpr int MT  = BB * SS;   // 4096 rows
constexpr int KCAT = 3 * DM;   // 3072 (hi|hi|lo concat K)

// Scratch (device globals: allocation-free)
__device__ float g_Q[BB * NH * SS * HDm];
__device__ float g_K[BB * NH * SS * HDm];
__device__ float g_V[BB * NH * SS * HDm];
__device__ __nv_bfloat16 g_Acat [MT * KCAT];    // [x_hi | x_hi | x_lo]
__device__ __nv_bfloat16 g_AOcat[MT * KCAT];    // attention out, same split
__device__ __nv_bfloat16 g_Bq[ND3 * KCAT];      // qkv weights^T [w_hi|w_lo|w_hi]
__device__ __nv_bfloat16 g_Bo[DM  * KCAT];      // out  weights^T

// ============================= MMA helpers =================================
#define LDSM_X4(R, addr)                                                      \
    asm volatile("ldmatrix.sync.aligned.m8n8.x4.shared.b16 {%0,%1,%2,%3}, [%4];" \
        : "=r"((R)[0]), "=r"((R)[1]), "=r"((R)[2]), "=r"((R)[3]) : "r"(addr))

#define MMA16816(C, A, b0, b1)                                                \
    asm volatile("mma.sync.aligned.m16n8k16.row.col.f32.bf16.bf16.f32 "       \
        "{%0,%1,%2,%3},{%4,%5,%6,%7},{%8,%9},{%0,%1,%2,%3};"                  \
        : "+f"((C)[0]), "+f"((C)[1]), "+f"((C)[2]), "+f"((C)[3])              \
        : "r"((A)[0]), "r"((A)[1]), "r"((A)[2]), "r"((A)[3]), "r"(b0), "r"(b1))

#define CP_ASYNC16(dst_u32, src_ptr)                                          \
    asm volatile("cp.async.cg.shared.global [%0], [%1], 16;"                  \
        :: "r"(dst_u32), "l"(src_ptr))
#define CP_COMMIT() asm volatile("cp.async.commit_group;" ::: "memory")
#define CP_WAIT1()  asm volatile("cp.async.wait_group 1;" ::: "memory")

__device__ __forceinline__ uint32_t smem_u32(const void* p) {
    uint32_t a;
    asm("{ .reg .u64 t; cvta.to.shared.u64 t, %1; cvt.u32.u64 %0, t; }"
        : "=r"(a) : "l"(p));
    return a;
}

// ============================ split helpers ================================
__device__ __forceinline__ void split_bf16(float x, __nv_bfloat16& hi, __nv_bfloat16& lo) {
    hi = __float2bfloat16_rn(x);
    lo = __float2bfloat16_rn(x - __bfloat162float(hi));
}

// ========================= conversion kernels ==============================
// x (MT x DM f32) -> A_cat (MT x 3072 bf16) = [hi | hi | lo]
__global__ __launch_bounds__(256) void conv_x(const float* __restrict__ X,
                                              __nv_bfloat16* __restrict__ A)
{
    const int idx = blockIdx.x * 256 + threadIdx.x;   // float4 index
    const int m  = idx >> 8;            // DM/4 = 256 float4 per row
    const int c  = (idx & 255) * 4;
    float4 v = *(const float4*)(X + m * DM + c);
    __nv_bfloat16 h[4], l[4];
    split_bf16(v.x, h[0], l[0]); split_bf16(v.y, h[1], l[1]);
    split_bf16(v.z, h[2], l[2]); split_bf16(v.w, h[3], l[3]);
    __nv_bfloat162 h01, h23, l01, l23;
    h01.x = h[0]; h01.y = h[1]; h23.x = h[2]; h23.y = h[3];
    l01.x = l[0]; l01.y = l[1]; l23.x = l[2]; l23.y = l[3];
    __nv_bfloat16* row = A + (size_t)m * KCAT;
    *(__nv_bfloat162*)(row + c)            = h01;
    *(__nv_bfloat162*)(row + c + 2)        = h23;
    *(__nv_bfloat162*)(row + DM + c)       = h01;
    *(__nv_bfloat162*)(row + DM + c + 2)   = h23;
    *(__nv_bfloat162*)(row + 2*DM + c)     = l01;
    *(__nv_bfloat162*)(row + 2*DM + c + 2) = l23;
}

// W (DM x Nn f32, row-major) -> Bcat (Nn x 3072 bf16) = [w_hi | w_lo | w_hi]
__global__ __launch_bounds__(256) void conv_w(const float* __restrict__ W,
                                              __nv_bfloat16* __restrict__ Bc,
                                              int Nn)
{
    __shared__ float t[32][33];
    const int tx = threadIdx.x, ty = threadIdx.y;
    const int n0 = blockIdx.x * 32, k0 = blockIdx.y * 32;
#pragma unroll
    for (int i = 0; i < 32; i += 8)
        t[ty + i][tx] = W[(size_t)(k0 + ty + i) * Nn + n0 + tx];
    __syncthreads();
#pragma unroll
    for (int i = 0; i < 32; i += 8) {
        const int n = n0 + ty + i;
        const float v = t[tx][ty + i];
        __nv_bfloat16 hi, lo;
        split_bf16(v, hi, lo);
        __nv_bfloat16* row = Bc + (size_t)n * KCAT + k0 + tx;
        row[0]      = hi;
        row[DM]     = lo;
        row[2 * DM] = hi;
    }
}

// ======================= HMMA bf16 GEMM ====================================
// C[M=4096][N] = A_cat[M][3072] @ B_cat[N][3072]^T + bias
// 128x128 CTA tile, 8 warps (4m x 2n), each warp 32x64.
// BK=32 chunks, 3-stage cp.async pipeline, 2 CTAs/SM.
constexpr int PIT = 80;                  // bytes per 32-bf16 row (64B + 16B pad)
constexpr int NCH = KCAT / 32;           // 96 chunks
constexpr int STG_A  = 128 * PIT;        // 10240 B
constexpr int STG_SZ = 2 * STG_A;        // 20480 B (A + B)
constexpr int NSTAGE = 3;
constexpr int TG_SMEM = NSTAGE * STG_SZ; // 61440 B

template <int EPI>
__global__ __launch_bounds__(256, 2) void tgemm(const __nv_bfloat16* __restrict__ Acat,
                                                const __nv_bfloat16* __restrict__ Bcat,
                                                const float* __restrict__ bias,
                                                float* __restrict__ Cout)
{
    extern __shared__ __align__(16) char smem[];
    const uint32_t sbase = smem_u32(smem);

    const int tid  = threadIdx.x;
    const int wid  = tid >> 5;
    const int lane = tid & 31;
    const int wm   = wid >> 1;          // 0..3 -> rows wm*32
    const int wn   = wid & 1;           // 0..1 -> cols wn*64
    const int n0   = blockIdx.x * 128;
    const int m0   = blockIdx.y * 128;

    const __nv_bfloat16* gA = Acat + (size_t)m0 * KCAT;
    const __nv_bfloat16* gB = Bcat + (size_t)n0 * KCAT;

    // cp.async staging: 128 rows x 64B per operand; 256 thr x 2 chunks of 16B.
    const int ldRow = tid >> 1;              // 0..127
    const int ldC   = (tid & 1) * 32;        // byte col 0 or 32
    const char* gArow = (const char*)(gA + (size_t)ldRow * KCAT);
    const char* gBrow = (const char*)(gB + (size_t)ldRow * KCAT);
    const uint32_t sArow = ldRow * PIT + ldC;

    // ldmatrix lane addresses (byte offsets within a stage)
    const int aOff0 = (wm * 32 +      (lane & 15)) * PIT + (lane >> 4) * 16;
    const int aOff1 = (wm * 32 + 16 + (lane & 15)) * PIT + (lane >> 4) * 16;
    const int bRow = wn * 64 + (lane & 7) + ((lane >> 4) << 3);
    const int bCol = ((lane >> 3) & 1) * 16;
    int bOff[4];
#pragma unroll
    for (int bt = 0; bt < 4; bt++)
        bOff[bt] = (bRow + bt * 16) * PIT + bCol;

    float c[2][8][4];
#pragma unroll
    for (int mt = 0; mt < 2; mt++)
#pragma unroll
        for (int nt = 0; nt < 8; nt++)
#pragma unroll
            for (int r = 0; r < 4; r++) c[mt][nt][r] = 0.f;

    // issue a stage's loads (chunk ch -> smem stage slot s)
    auto issue_stage = [&](int ch, int s) {
        const uint32_t base = sbase + s * STG_SZ;
        const int kb = ch * 64;                 // byte offset into K
        CP_ASYNC16(base + sArow,              gArow + kb + ldC);
        CP_ASYNC16(base + sArow + 16,         gArow + kb + ldC + 16);
        CP_ASYNC16(base + STG_A + sArow,      gBrow + kb + ldC);
        CP_ASYNC16(base + STG_A + sArow + 16, gBrow + kb + ldC + 16);
        CP_COMMIT();
    };

    // prologue: stages 0 and 1 in flight
    issue_stage(0, 0);
    issue_stage(1, 1);

    int s_cur = 0;
    for (int ch = 0; ch < NCH; ch++) {
        CP_WAIT1();            // stage ch resident (<=1 group pending)
        __syncthreads();       // all warps see it; prev stage reads done

        if (ch + 2 < NCH) {
            const int s_nxt = (s_cur + 2 >= NSTAGE) ? s_cur + 2 - NSTAGE : s_cur + 2;
            issue_stage(ch + 2, s_nxt);
        }

        const uint32_t baseA = sbase + s_cur * STG_SZ;
        const uint32_t baseB = baseA + STG_A;
#pragma unroll
        for (int ks = 0; ks < 2; ks++) {
            const int ko = ks * 32;   // 16 bf16 = 32 bytes
            uint32_t a[2][4];
            LDSM_X4(a[0], baseA + aOff0 + ko);
            LDSM_X4(a[1], baseA + aOff1 + ko);
            uint32_t bf[4][4];
#pragma unroll
            for (int bt = 0; bt < 4; bt++)
                LDSM_X4(bf[bt], baseB + bOff[bt] + ko);
#pragma unroll
            for (int mt = 0; mt < 2; mt++)
#pragma unroll
                for (int nt = 0; nt < 8; nt++) {
                    const uint32_t b0 = bf[nt >> 1][(nt & 1) * 2 + 0];
                    const uint32_t b1 = bf[nt >> 1][(nt & 1) * 2 + 1];
                    MMA16816(c[mt][nt], a[mt], b0, b1);
                }
        }

        s_cur = (s_cur + 1 >= NSTAGE) ? 0 : s_cur + 1;
    }

    // ---- epilogue ----
    const int g  = lane >> 2;       // 0..7
    const int tg = lane & 3;        // 0..3
#pragma unroll
    for (int mt = 0; mt < 2; mt++) {
#pragma unroll
        for (int half = 0; half < 2; half++) {     // row g / g+8
            const int m = m0 + wm * 32 + mt * 16 + g + half * 8;
            if (EPI == 0) {
                const int which = n0 >> 10;        // uniform per CTA
                float* dst = (which == 0) ? g_Q : (which == 1) ? g_K : g_V;
                const int bb = m >> 11;
                const int ss = m & (SS - 1);
#pragma unroll
                for (int nt = 0; nt < 8; nt++) {
                    const int n = n0 + wn * 64 + nt * 8 + tg * 2;
                    const int hh = (n & (DM - 1)) >> 6;
                    const int d0 = n & 63;
                    float2 v;
                    v.x = c[mt][nt][half * 2 + 0] + bias[n + 0];
                    v.y = c[mt][nt][half * 2 + 1] + bias[n + 1];
                    *(float2*)(dst + ((size_t)(bb * NH + hh) * SS + ss) * HDm + d0) = v;
                }
            } else {
#pragma unroll
                for (int nt = 0; nt < 8; nt++) {
                    const int n = n0 + wn * 64 + nt * 8 + tg * 2;
                    float2 v;
                    v.x = c[mt][nt][half * 2 + 0] + bias[n + 0];
                    v.y = c[mt][nt][half * 2 + 1] + bias[n + 1];
                    *(float2*)(Cout + (size_t)m * DM + n) = v;
                }
            }
        }
    }
}

// ---------------------------------------------------------------------------
// Windowed flash attention (fp32). Epilogue writes split-bf16 into g_AOcat.
// ---------------------------------------------------------------------------
constexpr int PITCH = 68;
constexpr int TSZ = 64 * PITCH;
constexpr int ATTN_SMEM_BYTES = 6 * TSZ * (int)sizeof(float);  // 104448

__device__ __forceinline__ void load_kv(const float* __restrict__ Kb,
                                        const float* __restrict__ Vb,
                                        float* __restrict__ Kst,
                                        float* __restrict__ Vs,
                                        int tid)
{
#pragma unroll
    for (int it = 0; it < 4; it++) {
        const int t = tid + it * 256;
        const int r = t >> 4;
        const int c = (t & 15) * 4;
        float4 kv = *(const float4*)(Kb + r * HDm + c);
        Kst[(c + 0) * PITCH + r] = kv.x;
        Kst[(c + 1) * PITCH + r] = kv.y;
        Kst[(c + 2) * PITCH + r] = kv.z;
        Kst[(c + 3) * PITCH + r] = kv.w;
        float4 vv = *(const float4*)(Vb + r * HDm + c);
        *(float4*)&Vs[r * PITCH + c] = vv;
    }
}

__global__ __launch_bounds__(256) void attn_kernel()
{
    extern __shared__ float smf[];
    float* Qst = smf;
    float* Pst = smf + 5 * TSZ;

    const int tid = threadIdx.x;
    const int ty  = tid >> 4;
    const int tx  = tid & 15;
    const int q0  = blockIdx.x * 64;
    const int h   = blockIdx.y;
    const int b   = blockIdx.z;

    const float* Qg = g_Q + (size_t)(b * NH + h) * SS * HDm;
    const float* Kg = g_K + (size_t)(b * NH + h) * SS * HDm;
    const float* Vg = g_V + (size_t)(b * NH + h) * SS * HDm;

#pragma unroll
    for (int it = 0; it < 4; it++) {
        const int t = tid + it * 256;
        const int r = t >> 4;
        const int c = (t & 15) * 4;
        float4 v = *(const float4*)(Qg + (q0 + r) * HDm + c);
        Qst[(c + 0) * PITCH + r] = v.x * 0.125f;
        Qst[(c + 1) * PITCH + r] = v.y * 0.125f;
        Qst[(c + 2) * PITCH + r] = v.z * 0.125f;
        Qst[(c + 3) * PITCH + r] = v.w * 0.125f;
    }

    float m_prev[4], lsum[4], o[4][4];
#pragma unroll
    for (int i = 0; i < 4; i++) {
        m_prev[i] = -1e30f;
        lsum[i] = 0.f;
#pragma unroll
        for (int j = 0; j < 4; j++) o[i][j] = 0.f;
    }

    const int kb_start = (q0 >= WIN) ? ((q0 - (WIN - 1)) >> 6) : 0;
    const int kb_end   = q0 >> 6;

    load_kv(Kg + kb_start * 64 * HDm, Vg + kb_start * 64 * HDm,
            smf + 1 * TSZ, smf + 2 * TSZ, tid);
    __syncthreads();

    int buf = 0;
    for (int kb = kb_start; kb <= kb_end; kb++) {
        float* Kst = smf + (1 + 2 * buf) * TSZ;
        float* Vs  = Kst + TSZ;

        if (kb < kb_end) {
            float* Kn = smf + (1 + 2 * (buf ^ 1)) * TSZ;
            load_kv(Kg + (kb + 1) * 64 * HDm, Vg + (kb + 1) * 64 * HDm,
                    Kn, Kn + TSZ, tid);
        }

        float sacc[4][4];
#pragma unroll
        for (int i = 0; i < 4; i++)
#pragma unroll
            for (int j = 0; j < 4; j++) sacc[i][j] = 0.f;

#pragma unroll 16
        for (int kd = 0; kd < 64; kd++) {
            float4 qf = *(const float4*)&Qst[kd * PITCH + ty * 4];
            float4 kf = *(const float4*)&Kst[kd * PITCH + tx * 4];
            const float qa[4] = {qf.x, qf.y, qf.z, qf.w};
            const float ka[4] = {kf.x, kf.y, kf.z, kf.w};
#pragma unroll
            for (int i = 0; i < 4; i++)
#pragma unroll
                for (int j = 0; j < 4; j++)
                    sacc[i][j] = fmaf(qa[i], ka[j], sacc[i][j]);
        }

        const int diff = q0 - kb * 64;
        const bool full = (diff >= 63) && (diff + 63 < WIN);

#pragma unroll
        for (int i = 0; i < 4; i++) {
            float sv[4];
            float rowmax = -1e30f;
            if (full) {
#pragma unroll
                for (int j = 0; j < 4; j++) {
                    sv[j] = sacc[i][j];
                    rowmax = fmaxf(rowmax, sv[j]);
                }
            } else {
                const int qg = q0 + ty * 4 + i;
#pragma unroll
                for (int j = 0; j < 4; j++) {
                    const int jg = kb * 64 + tx * 4 + j;
                    const int d  = qg - jg;
                    const bool valid = (d >= 0) && (d < WIN);
                    sv[j] = valid ? sacc[i][j] : -1e30f;
                    rowmax = fmaxf(rowmax, sv[j]);
                }
            }
#pragma unroll
            for (int off = 8; off > 0; off >>= 1)
                rowmax = fmaxf(rowmax, __shfl_xor_sync(0xffffffffu, rowmax, off));
            const float mn = fmaxf(m_prev[i], rowmax);
            float psum = 0.f;
#pragma unroll
            for (int j = 0; j < 4; j++) {
                const float p = (sv[j] > -1e29f) ? __expf(sv[j] - mn) : 0.f;
                psum += p;
                Pst[(tx * 4 + j) * PITCH + ty * 4 + i] = p;
            }
#pragma unroll
            for (int off = 8; off > 0; off >>= 1)
                psum += __shfl_xor_sync(0xffffffffu, psum, off);
            const float corr = __expf(m_prev[i] - mn);
            lsum[i] = lsum[i] * corr + psum;
            m_prev[i] = mn;
#pragma unroll
            for (int j = 0; j < 4; j++) o[i][j] *= corr;
        }
        __syncthreads();

#pragma unroll 16
        for (int k = 0; k < 64; k++) {
            float4 pf = *(const float4*)&Pst[k * PITCH + ty * 4];
            float4 vf = *(const float4*)&Vs[k * PITCH + tx * 4];
            const float pa[4] = {pf.x, pf.y, pf.z, pf.w};
            const float va[4] = {vf.x, vf.y, vf.z, vf.w};
#pragma unroll
            for (int i = 0; i < 4; i++)
#pragma unroll
                for (int j = 0; j < 4; j++)
                    o[i][j] = fmaf(pa[i], va[j], o[i][j]);
        }
        __syncthreads();
        buf ^= 1;
    }

    // epilogue: normalize, split to bf16 hi/lo, write A_cat layout [hi|hi|lo]
#pragma unroll
    for (int i = 0; i < 4; i++) {
        const int qg = q0 + ty * 4 + i;
        const float inv = 1.f / lsum[i];
        float v[4];
#pragma unroll
        for (int j = 0; j < 4; j++) v[j] = o[i][j] * inv;
        __nv_bfloat16 h4[4], l4[4];
#pragma unroll
        for (int j = 0; j < 4; j++) split_bf16(v[j], h4[j], l4[j]);
        __nv_bfloat162 h01, h23, l01, l23;
        h01.x = h4[0]; h01.y = h4[1]; h23.x = h4[2]; h23.y = h4[3];
        l01.x = l4[0]; l01.y = l4[1]; l23.x = l4[2]; l23.y = l4[3];
        __nv_bfloat16* row = g_AOcat + (size_t)(b * SS + qg) * KCAT + h * HDm + tx * 4;
        *(__nv_bfloat162*)(row)              = h01;
        *(__nv_bfloat162*)(row + 2)          = h23;
        *(__nv_bfloat162*)(row + DM)         = h01;
        *(__nv_bfloat162*)(row + DM + 2)     = h23;
        *(__nv_bfloat162*)(row + 2*DM)       = l01;
        *(__nv_bfloat162*)(row + 2*DM + 2)   = l23;
    }
}

// ---------------------------------------------------------------------------
extern "C" void kernel_launch(void* const* d_in, const int* in_sizes, int n_in,
                              void* d_out, int out_size)
{
    const float* x     = (const float*)d_in[0];
    const float* qkvw  = (const float*)d_in[1];
    const float* qkvb  = (const float*)d_in[2];
    const float* outw  = (const float*)d_in[3];
    const float* outb  = (const float*)d_in[4];
    float* out = (float*)d_out;

    cudaFuncSetAttribute(attn_kernel, cudaFuncAttributeMaxDynamicSharedMemorySize,
                         ATTN_SMEM_BYTES);
    cudaFuncSetAttribute(tgemm<0>, cudaFuncAttributeMaxDynamicSharedMemorySize, TG_SMEM);
    cudaFuncSetAttribute(tgemm<1>, cudaFuncAttributeMaxDynamicSharedMemorySize, TG_SMEM);

    __nv_bfloat16 *Acat, *AOcat, *Bq, *Bo;
    cudaGetSymbolAddress((void**)&Acat,  g_Acat);
    cudaGetSymbolAddress((void**)&AOcat, g_AOcat);
    cudaGetSymbolAddress((void**)&Bq,    g_Bq);
    cudaGetSymbolAddress((void**)&Bo,    g_Bo);

    // 0) split-precision conversions
    conv_x<<<MT * DM / 1024, 256>>>(x, Acat);
    conv_w<<<dim3(ND3 / 32, DM / 32), dim3(32, 8)>>>(qkvw, Bq, ND3);
    conv_w<<<dim3(DM  / 32, DM / 32), dim3(32, 8)>>>(outw, Bo, DM);

    // 1) QKV projection (bf16 HMMA, scatter to Q/K/V)
    tgemm<0><<<dim3(ND3 / 128, MT / 128), 256, TG_SMEM>>>(Acat, Bq, qkvb, nullptr);

    // 2) Windowed attention (fp32), writes split-bf16 AO
    attn_kernel<<<dim3(SS / 64, NH, BB), 256, ATTN_SMEM_BYTES>>>();

    // 3) Output projection (bf16 HMMA)
    tgemm<1><<<dim3(DM / 128, MT / 128), 256, TG_SMEM>>>(AOcat, Bo, outb, out);
}

// round 14
// speedup vs baseline: 1.6920x; 1.1068x over previous
#include <cuda_runtime.h>
#include <cuda_bf16.h>
#include <cstdint>

// ---------------------------------------------------------------------------
// SlidingWindowAttention on GB300 (sm_103 base target — no tcgen05)
// R13: split-precision bf16 HMMA GEMMs restructured as 4-tile/3-product
//      (K=1024, A_hi/A_lo/B_hi/B_lo per chunk) — 33% less L2 traffic and
//      3x fewer pipeline boundaries than the K-concat form.
//      fp32 flash attention unchanged.
// ---------------------------------------------------------------------------

constexpr int BB  = 2;
constexpr int SS  = 2048;
constexpr int NH  = 16;
constexpr int HDm = 64;
constexpr int DM  = 1024;      // NH*HDm
constexpr int ND3 = 3072;      // 3*DM
constexpr int WIN = 512;
constexpr int MT  = BB * SS;   // 4096 rows

// Scratch (device globals: allocation-free)
__device__ float g_Q[BB * NH * SS * HDm];
__device__ float g_K[BB * NH * SS * HDm];
__device__ float g_V[BB * NH * SS * HDm];
__device__ __nv_bfloat16 g_Ahi [MT * DM];
__device__ __nv_bfloat16 g_Alo [MT * DM];
__device__ __nv_bfloat16 g_AOhi[MT * DM];
__device__ __nv_bfloat16 g_AOlo[MT * DM];
__device__ __nv_bfloat16 g_Bqhi[ND3 * DM];   // qkv weights^T rows (K contiguous)
__device__ __nv_bfloat16 g_Bqlo[ND3 * DM];
__device__ __nv_bfloat16 g_Bohi[DM * DM];    // out weights^T
__device__ __nv_bfloat16 g_Bolo[DM * DM];

// ============================= MMA helpers =================================
#define LDSM_X4(R, addr)                                                      \
    asm volatile("ldmatrix.sync.aligned.m8n8.x4.shared.b16 {%0,%1,%2,%3}, [%4];" \
        : "=r"((R)[0]), "=r"((R)[1]), "=r"((R)[2]), "=r"((R)[3]) : "r"(addr))

#define MMA16816(C, A, b0, b1)                                                \
    asm volatile("mma.sync.aligned.m16n8k16.row.col.f32.bf16.bf16.f32 "       \
        "{%0,%1,%2,%3},{%4,%5,%6,%7},{%8,%9},{%0,%1,%2,%3};"                  \
        : "+f"((C)[0]), "+f"((C)[1]), "+f"((C)[2]), "+f"((C)[3])              \
        : "r"((A)[0]), "r"((A)[1]), "r"((A)[2]), "r"((A)[3]), "r"(b0), "r"(b1))

#define CP_ASYNC16(dst_u32, src_ptr)                                          \
    asm volatile("cp.async.cg.shared.global [%0], [%1], 16;"                  \
        :: "r"(dst_u32), "l"(src_ptr))
#define CP_COMMIT() asm volatile("cp.async.commit_group;" ::: "memory")
#define CP_WAIT0()  asm volatile("cp.async.wait_group 0;" ::: "memory")

__device__ __forceinline__ uint32_t smem_u32(const void* p) {
    uint32_t a;
    asm("{ .reg .u64 t; cvta.to.shared.u64 t, %1; cvt.u32.u64 %0, t; }"
        : "=r"(a) : "l"(p));
    return a;
}

// ============================ split helpers ================================
__device__ __forceinline__ void split_bf16(float x, __nv_bfloat16& hi, __nv_bfloat16& lo) {
    hi = __float2bfloat16_rn(x);
    lo = __float2bfloat16_rn(x - __bfloat162float(hi));
}

// ========================= conversion kernels ==============================
// x (MT x DM f32) -> Ahi / Alo (MT x DM bf16)
__global__ __launch_bounds__(256) void conv_x(const float* __restrict__ X,
                                              __nv_bfloat16* __restrict__ Ahi,
                                              __nv_bfloat16* __restrict__ Alo)
{
    const int idx = blockIdx.x * 256 + threadIdx.x;   // float4 index
    const int m  = idx >> 8;            // DM/4 = 256 float4 per row
    const int c  = (idx & 255) * 4;
    float4 v = *(const float4*)(X + m * DM + c);
    __nv_bfloat16 h[4], l[4];
    split_bf16(v.x, h[0], l[0]); split_bf16(v.y, h[1], l[1]);
    split_bf16(v.z, h[2], l[2]); split_bf16(v.w, h[3], l[3]);
    __nv_bfloat162 h01, h23, l01, l23;
    h01.x = h[0]; h01.y = h[1]; h23.x = h[2]; h23.y = h[3];
    l01.x = l[0]; l01.y = l[1]; l23.x = l[2]; l23.y = l[3];
    *(__nv_bfloat162*)(Ahi + (size_t)m * DM + c)     = h01;
    *(__nv_bfloat162*)(Ahi + (size_t)m * DM + c + 2) = h23;
    *(__nv_bfloat162*)(Alo + (size_t)m * DM + c)     = l01;
    *(__nv_bfloat162*)(Alo + (size_t)m * DM + c + 2) = l23;
}

// W (DM x Nn f32, row-major) -> Bhi/Blo (Nn x DM bf16, K contiguous)
__global__ __launch_bounds__(256) void conv_w(const float* __restrict__ W,
                                              __nv_bfloat16* __restrict__ Bhi,
                                              __nv_bfloat16* __restrict__ Blo,
                                              int Nn)
{
    __shared__ float t[32][33];
    const int tx = threadIdx.x, ty = threadIdx.y;
    const int n0 = blockIdx.x * 32, k0 = blockIdx.y * 32;
#pragma unroll
    for (int i = 0; i < 32; i += 8)
        t[ty + i][tx] = W[(size_t)(k0 + ty + i) * Nn + n0 + tx];
    __syncthreads();
#pragma unroll
    for (int i = 0; i < 32; i += 8) {
        const int n = n0 + ty + i;
        const float v = t[tx][ty + i];
        __nv_bfloat16 hi, lo;
        split_bf16(v, hi, lo);
        Bhi[(size_t)n * DM + k0 + tx] = hi;
        Blo[(size_t)n * DM + k0 + tx] = lo;
    }
}

// ======================= HMMA bf16 GEMM ====================================
// C[M=4096][N] = (Ahi+Alo)[M][1024] @ (Bhi+Blo)[N][1024]^T + bias
//              ≈ Ahi·Bhi + Alo·Bhi + Ahi·Blo      (lo·lo dropped, ~2^-16)
// 128x128 CTA tile, 8 warps (4m x 2n). BK=32 chunks over K=1024 (32 chunks),
// 4 tiles/chunk, 2-stage cp.async, 2 CTAs/SM.
constexpr int PIT   = 80;                // bytes per 32-bf16 row (64B + 16B pad)
constexpr int NCH   = DM / 32;           // 32 chunks
constexpr int TILE  = 128 * PIT;         // 10240 B
constexpr int OFF_ALO = TILE;
constexpr int OFF_BHI = 2 * TILE;
constexpr int OFF_BLO = 3 * TILE;
constexpr int STG   = 4 * TILE;          // 40960 B per stage
constexpr int TG_SMEM = 2 * STG;         // 81920 B

template <int EPI>
__global__ __launch_bounds__(256, 2) void tgemm(const __nv_bfloat16* __restrict__ Ahi,
                                                const __nv_bfloat16* __restrict__ Alo,
                                                const __nv_bfloat16* __restrict__ Bhi,
                                                const __nv_bfloat16* __restrict__ Blo,
                                                const float* __restrict__ bias,
                                                float* __restrict__ Cout)
{
    extern __shared__ __align__(16) char smem[];
    const uint32_t sbase = smem_u32(smem);

    const int tid  = threadIdx.x;
    const int wid  = tid >> 5;
    const int lane = tid & 31;
    const int wm   = wid >> 1;          // 0..3 -> rows wm*32
    const int wn   = wid & 1;           // 0..1 -> cols wn*64
    const int n0   = blockIdx.x * 128;
    const int m0   = blockIdx.y * 128;

    // cp.async staging: per tile 128 rows x 64B; 256 thr x 2 x 16B each.
    const int ldRow = tid >> 1;              // 0..127
    const int ldC   = (tid & 1) * 32;        // byte col 0 or 32
    const char* gAh = (const char*)(Ahi + (size_t)(m0 + ldRow) * DM);
    const char* gAl = (const char*)(Alo + (size_t)(m0 + ldRow) * DM);
    const char* gBh = (const char*)(Bhi + (size_t)(n0 + ldRow) * DM);
    const char* gBl = (const char*)(Blo + (size_t)(n0 + ldRow) * DM);
    const uint32_t rowOff = ldRow * PIT + ldC;

    // ldmatrix lane addresses (byte offsets within a tile)
    const int aOff0 = (wm * 32 +      (lane & 15)) * PIT + (lane >> 4) * 16;
    const int aOff1 = (wm * 32 + 16 + (lane & 15)) * PIT + (lane >> 4) * 16;
    const int bRow = wn * 64 + (lane & 7) + ((lane >> 4) << 3);
    const int bCol = ((lane >> 3) & 1) * 16;
    int bOff[4];
#pragma unroll
    for (int bt = 0; bt < 4; bt++)
        bOff[bt] = (bRow + bt * 16) * PIT + bCol;

    float c[2][8][4];
#pragma unroll
    for (int mt = 0; mt < 2; mt++)
#pragma unroll
        for (int nt = 0; nt < 8; nt++)
#pragma unroll
            for (int r = 0; r < 4; r++) c[mt][nt][r] = 0.f;

    auto issue_stage = [&](int ch, int s) {
        const uint32_t base = sbase + s * STG;
        const int kb = ch * 64;              // byte offset into K
        CP_ASYNC16(base + rowOff,                 gAh + kb + ldC);
        CP_ASYNC16(base + rowOff + 16,            gAh + kb + ldC + 16);
        CP_ASYNC16(base + OFF_ALO + rowOff,       gAl + kb + ldC);
        CP_ASYNC16(base + OFF_ALO + rowOff + 16,  gAl + kb + ldC + 16);
        CP_ASYNC16(base + OFF_BHI + rowOff,       gBh + kb + ldC);
        CP_ASYNC16(base + OFF_BHI + rowOff + 16,  gBh + kb + ldC + 16);
        CP_ASYNC16(base + OFF_BLO + rowOff,       gBl + kb + ldC);
        CP_ASYNC16(base + OFF_BLO + rowOff + 16,  gBl + kb + ldC + 16);
        CP_COMMIT();
    };

    issue_stage(0, 0);

    int s = 0;
    for (int ch = 0; ch < NCH; ch++) {
        CP_WAIT0();            // stage ch resident (only pending group)
        __syncthreads();       // visible to all; all warps done with ch-1
        if (ch + 1 < NCH) issue_stage(ch + 1, s ^ 1);  // overlaps compute below

        const uint32_t sb = sbase + s * STG;
#pragma unroll
        for (int ks = 0; ks < 2; ks++) {
            const int ko = ks * 32;   // 16 bf16 = 32 bytes
            uint32_t ah[2][4], bh[4][4];
            LDSM_X4(ah[0], sb + aOff0 + ko);
            LDSM_X4(ah[1], sb + aOff1 + ko);
#pragma unroll
            for (int bt = 0; bt < 4; bt++)
                LDSM_X4(bh[bt], sb + OFF_BHI + bOff[bt] + ko);
            // hi * hi
#pragma unroll
            for (int mt = 0; mt < 2; mt++)
#pragma unroll
                for (int nt = 0; nt < 8; nt++)
                    MMA16816(c[mt][nt], ah[mt],
                             bh[nt >> 1][(nt & 1) * 2 + 0],
                             bh[nt >> 1][(nt & 1) * 2 + 1]);
            // lo * hi
            {
                uint32_t al[2][4];
                LDSM_X4(al[0], sb + OFF_ALO + aOff0 + ko);
                LDSM_X4(al[1], sb + OFF_ALO + aOff1 + ko);
#pragma unroll
                for (int mt = 0; mt < 2; mt++)
#pragma unroll
                    for (int nt = 0; nt < 8; nt++)
                        MMA16816(c[mt][nt], al[mt],
                                 bh[nt >> 1][(nt & 1) * 2 + 0],
                                 bh[nt >> 1][(nt & 1) * 2 + 1]);
            }
            // hi * lo
            {
                uint32_t bl[4][4];
#pragma unroll
                for (int bt = 0; bt < 4; bt++)
                    LDSM_X4(bl[bt], sb + OFF_BLO + bOff[bt] + ko);
#pragma unroll
                for (int mt = 0; mt < 2; mt++)
#pragma unroll
                    for (int nt = 0; nt < 8; nt++)
                        MMA16816(c[mt][nt], ah[mt],
                                 bl[nt >> 1][(nt & 1) * 2 + 0],
                                 bl[nt >> 1][(nt & 1) * 2 + 1]);
            }
        }
        s ^= 1;
    }

    // ---- epilogue ----
    const int g  = lane >> 2;       // 0..7
    const int tg = lane & 3;        // 0..3
#pragma unroll
    for (int mt = 0; mt < 2; mt++) {
#pragma unroll
        for (int half = 0; half < 2; half++) {     // row g / g+8
            const int m = m0 + wm * 32 + mt * 16 + g + half * 8;
            if (EPI == 0) {
                const int which = n0 >> 10;        // uniform per CTA
                float* dst = (which == 0) ? g_Q : (which == 1) ? g_K : g_V;
                const int bb = m >> 11;
                const int ss = m & (SS - 1);
#pragma unroll
                for (int nt = 0; nt < 8; nt++) {
                    const int n = n0 + wn * 64 + nt * 8 + tg * 2;
                    const int hh = (n & (DM - 1)) >> 6;
                    const int d0 = n & 63;
                    float2 v;
                    v.x = c[mt][nt][half * 2 + 0] + bias[n + 0];
                    v.y = c[mt][nt][half * 2 + 1] + bias[n + 1];
                    *(float2*)(dst + ((size_t)(bb * NH + hh) * SS + ss) * HDm + d0) = v;
                }
            } else {
#pragma unroll
                for (int nt = 0; nt < 8; nt++) {
                    const int n = n0 + wn * 64 + nt * 8 + tg * 2;
                    float2 v;
                    v.x = c[mt][nt][half * 2 + 0] + bias[n + 0];
                    v.y = c[mt][nt][half * 2 + 1] + bias[n + 1];
                    *(float2*)(Cout + (size_t)m * DM + n) = v;
                }
            }
        }
    }
}

// ---------------------------------------------------------------------------
// Windowed flash attention (fp32). Epilogue writes split-bf16 AOhi/AOlo.
// ---------------------------------------------------------------------------
constexpr int PITCH = 68;
constexpr int TSZ = 64 * PITCH;
constexpr int ATTN_SMEM_BYTES = 6 * TSZ * (int)sizeof(float);  // 104448

__device__ __forceinline__ void load_kv(const float* __restrict__ Kb,
                                        const float* __restrict__ Vb,
                                        float* __restrict__ Kst,
                                        float* __restrict__ Vs,
                                        int tid)
{
#pragma unroll
    for (int it = 0; it < 4; it++) {
        const int t = tid + it * 256;
        const int r = t >> 4;
        const int c = (t & 15) * 4;
        float4 kv = *(const float4*)(Kb + r * HDm + c);
        Kst[(c + 0) * PITCH + r] = kv.x;
        Kst[(c + 1) * PITCH + r] = kv.y;
        Kst[(c + 2) * PITCH + r] = kv.z;
        Kst[(c + 3) * PITCH + r] = kv.w;
        float4 vv = *(const float4*)(Vb + r * HDm + c);
        *(float4*)&Vs[r * PITCH + c] = vv;
    }
}

__global__ __launch_bounds__(256) void attn_kernel()
{
    extern __shared__ float smf[];
    float* Qst = smf;
    float* Pst = smf + 5 * TSZ;

    const int tid = threadIdx.x;
    const int ty  = tid >> 4;
    const int tx  = tid & 15;
    const int q0  = blockIdx.x * 64;
    const int h   = blockIdx.y;
    const int b   = blockIdx.z;

    const float* Qg = g_Q + (size_t)(b * NH + h) * SS * HDm;
    const float* Kg = g_K + (size_t)(b * NH + h) * SS * HDm;
    const float* Vg = g_V + (size_t)(b * NH + h) * SS * HDm;

#pragma unroll
    for (int it = 0; it < 4; it++) {
        const int t = tid + it * 256;
        const int r = t >> 4;
        const int c = (t & 15) * 4;
        float4 v = *(const float4*)(Qg + (q0 + r) * HDm + c);
        Qst[(c + 0) * PITCH + r] = v.x * 0.125f;
        Qst[(c + 1) * PITCH + r] = v.y * 0.125f;
        Qst[(c + 2) * PITCH + r] = v.z * 0.125f;
        Qst[(c + 3) * PITCH + r] = v.w * 0.125f;
    }

    float m_prev[4], lsum[4], o[4][4];
#pragma unroll
    for (int i = 0; i < 4; i++) {
        m_prev[i] = -1e30f;
        lsum[i] = 0.f;
#pragma unroll
        for (int j = 0; j < 4; j++) o[i][j] = 0.f;
    }

    const int kb_start = (q0 >= WIN) ? ((q0 - (WIN - 1)) >> 6) : 0;
    const int kb_end   = q0 >> 6;

    load_kv(Kg + kb_start * 64 * HDm, Vg + kb_start * 64 * HDm,
            smf + 1 * TSZ, smf + 2 * TSZ, tid);
    __syncthreads();

    int buf = 0;
    for (int kb = kb_start; kb <= kb_end; kb++) {
        float* Kst = smf + (1 + 2 * buf) * TSZ;
        float* Vs  = Kst + TSZ;

        if (kb < kb_end) {
            float* Kn = smf + (1 + 2 * (buf ^ 1)) * TSZ;
            load_kv(Kg + (kb + 1) * 64 * HDm, Vg + (kb + 1) * 64 * HDm,
                    Kn, Kn + TSZ, tid);
        }

        float sacc[4][4];
#pragma unroll
        for (int i = 0; i < 4; i++)
#pragma unroll
            for (int j = 0; j < 4; j++) sacc[i][j] = 0.f;

#pragma unroll 16
        for (int kd = 0; kd < 64; kd++) {
            float4 qf = *(const float4*)&Qst[kd * PITCH + ty * 4];
            float4 kf = *(const float4*)&Kst[kd * PITCH + tx * 4];
            const float qa[4] = {qf.x, qf.y, qf.z, qf.w};
            const float ka[4] = {kf.x, kf.y, kf.z, kf.w};
#pragma unroll
            for (int i = 0; i < 4; i++)
#pragma unroll
                for (int j = 0; j < 4; j++)
                    sacc[i][j] = fmaf(qa[i], ka[j], sacc[i][j]);
        }

        const int diff = q0 - kb * 64;
        const bool full = (diff >= 63) && (diff + 63 < WIN);

#pragma unroll
        for (int i = 0; i < 4; i++) {
            float sv[4];
            float rowmax = -1e30f;
            if (full) {
#pragma unroll
                for (int j = 0; j < 4; j++) {
                    sv[j] = sacc[i][j];
                    rowmax = fmaxf(rowmax, sv[j]);
                }
            } else {
                const int qg = q0 + ty * 4 + i;
#pragma unroll
                for (int j = 0; j < 4; j++) {
                    const int jg = kb * 64 + tx * 4 + j;
                    const int d  = qg - jg;
                    const bool valid = (d >= 0) && (d < WIN);
                    sv[j] = valid ? sacc[i][j] : -1e30f;
                    rowmax = fmaxf(rowmax, sv[j]);
                }
            }
#pragma unroll
            for (int off = 8; off > 0; off >>= 1)
                rowmax = fmaxf(rowmax, __shfl_xor_sync(0xffffffffu, rowmax, off));
            const float mn = fmaxf(m_prev[i], rowmax);
            float psum = 0.f;
#pragma unroll
            for (int j = 0; j < 4; j++) {
                const float p = (sv[j] > -1e29f) ? __expf(sv[j] - mn) : 0.f;
                psum += p;
                Pst[(tx * 4 + j) * PITCH + ty * 4 + i] = p;
            }
#pragma unroll
            for (int off = 8; off > 0; off >>= 1)
                psum += __shfl_xor_sync(0xffffffffu, psum, off);
            const float corr = __expf(m_prev[i] - mn);
            lsum[i] = lsum[i] * corr + psum;
            m_prev[i] = mn;
#pragma unroll
            for (int j = 0; j < 4; j++) o[i][j] *= corr;
        }
        __syncthreads();

#pragma unroll 16
        for (int k = 0; k < 64; k++) {
            float4 pf = *(const float4*)&Pst[k * PITCH + ty * 4];
            float4 vf = *(const float4*)&Vs[k * PITCH + tx * 4];
            const float pa[4] = {pf.x, pf.y, pf.z, pf.w};
            const float va[4] = {vf.x, vf.y, vf.z, vf.w};
#pragma unroll
            for (int i = 0; i < 4; i++)
#pragma unroll
                for (int j = 0; j < 4; j++)
                    o[i][j] = fmaf(pa[i], va[j], o[i][j]);
        }
        __syncthreads();
        buf ^= 1;
    }

    // epilogue: normalize, split to bf16 hi/lo, write AOhi / AOlo
#pragma unroll
    for (int i = 0; i < 4; i++) {
        const int qg = q0 + ty * 4 + i;
        const float inv = 1.f / lsum[i];
        float v[4];
#pragma unroll
        for (int j = 0; j < 4; j++) v[j] = o[i][j] * inv;
        __nv_bfloat16 h4[4], l4[4];
#pragma unroll
        for (int j = 0; j < 4; j++) split_bf16(v[j], h4[j], l4[j]);
        __nv_bfloat162 h01, h23, l01, l23;
        h01.x = h4[0]; h01.y = h4[1]; h23.x = h4[2]; h23.y = h4[3];
        l01.x = l4[0]; l01.y = l4[1]; l23.x = l4[2]; l23.y = l4[3];
        const size_t off = (size_t)(b * SS + qg) * DM + h * HDm + tx * 4;
        *(__nv_bfloat162*)(g_AOhi + off)     = h01;
        *(__nv_bfloat162*)(g_AOhi + off + 2) = h23;
        *(__nv_bfloat162*)(g_AOlo + off)     = l01;
        *(__nv_bfloat162*)(g_AOlo + off + 2) = l23;
    }
}

// ---------------------------------------------------------------------------
extern "C" void kernel_launch(void* const* d_in, const int* in_sizes, int n_in,
                              void* d_out, int out_size)
{
    const float* x     = (const float*)d_in[0];
    const float* qkvw  = (const float*)d_in[1];
    const float* qkvb  = (const float*)d_in[2];
    const float* outw  = (const float*)d_in[3];
    const float* outb  = (const float*)d_in[4];
    float* out = (float*)d_out;

    cudaFuncSetAttribute(attn_kernel, cudaFuncAttributeMaxDynamicSharedMemorySize,
                         ATTN_SMEM_BYTES);
    cudaFuncSetAttribute(tgemm<0>, cudaFuncAttributeMaxDynamicSharedMemorySize, TG_SMEM);
    cudaFuncSetAttribute(tgemm<1>, cudaFuncAttributeMaxDynamicSharedMemorySize, TG_SMEM);

    __nv_bfloat16 *Ahi, *Alo, *AOhi, *AOlo, *Bqhi, *Bqlo, *Bohi, *Bolo;
    cudaGetSymbolAddress((void**)&Ahi,  g_Ahi);
    cudaGetSymbolAddress((void**)&Alo,  g_Alo);
    cudaGetSymbolAddress((void**)&AOhi, g_AOhi);
    cudaGetSymbolAddress((void**)&AOlo, g_AOlo);
    cudaGetSymbolAddress((void**)&Bqhi, g_Bqhi);
    cudaGetSymbolAddress((void**)&Bqlo, g_Bqlo);
    cudaGetSymbolAddress((void**)&Bohi, g_Bohi);
    cudaGetSymbolAddress((void**)&Bolo, g_Bolo);

    // 0) split-precision conversions
    conv_x<<<MT * DM / 1024, 256>>>(x, Ahi, Alo);
    conv_w<<<dim3(ND3 / 32, DM / 32), dim3(32, 8)>>>(qkvw, Bqhi, Bqlo, ND3);
    conv_w<<<dim3(DM  / 32, DM / 32), dim3(32, 8)>>>(outw, Bohi, Bolo, DM);

    // 1) QKV projection (bf16 HMMA 3-product, scatter to Q/K/V)
    tgemm<0><<<dim3(ND3 / 128, MT / 128), 256, TG_SMEM>>>(Ahi, Alo, Bqhi, Bqlo,
                                                          qkvb, nullptr);

    // 2) Windowed attention (fp32), writes split-bf16 AO
    attn_kernel<<<dim3(SS / 64, NH, BB), 256, ATTN_SMEM_BYTES>>>();

    // 3) Output projection (bf16 HMMA 3-product)
    tgemm<1><<<dim3(DM / 128, MT / 128), 256, TG_SMEM>>>(AOhi, AOlo, Bohi, Bolo,
                                                         outb, out);
}

// round 15
// speedup vs baseline: 2.3876x; 1.4111x over previous
#include <cuda_runtime.h>
#include <cuda_bf16.h>
#include <cstdint>

// ---------------------------------------------------------------------------
// SlidingWindowAttention on GB300 (sm_103 base target — no tcgen05)
// R14: attention converted to split-bf16 HMMA (FA2-style, P in registers);
//      QKV GEMM epilogue emits pre-split bf16 Q/K/V (Q pre-scaled by 1/8).
//      GEMMs otherwise unchanged from R13 (4-tile/3-product, cp.async).
// ---------------------------------------------------------------------------

constexpr int BB  = 2;
constexpr int SS  = 2048;
constexpr int NH  = 16;
constexpr int HDm = 64;
constexpr int DM  = 1024;      // NH*HDm
constexpr int ND3 = 3072;      // 3*DM
constexpr int WIN = 512;
constexpr int MT  = BB * SS;   // 4096 rows

// Scratch (device globals: allocation-free)
__device__ __nv_bfloat16 g_Qhi[BB * NH * SS * HDm];
__device__ __nv_bfloat16 g_Qlo[BB * NH * SS * HDm];
__device__ __nv_bfloat16 g_Khi[BB * NH * SS * HDm];
__device__ __nv_bfloat16 g_Klo[BB * NH * SS * HDm];
__device__ __nv_bfloat16 g_Vhi[BB * NH * SS * HDm];
__device__ __nv_bfloat16 g_Vlo[BB * NH * SS * HDm];
__device__ __nv_bfloat16 g_Ahi [MT * DM];
__device__ __nv_bfloat16 g_Alo [MT * DM];
__device__ __nv_bfloat16 g_AOhi[MT * DM];
__device__ __nv_bfloat16 g_AOlo[MT * DM];
__device__ __nv_bfloat16 g_Bqhi[ND3 * DM];
__device__ __nv_bfloat16 g_Bqlo[ND3 * DM];
__device__ __nv_bfloat16 g_Bohi[DM * DM];
__device__ __nv_bfloat16 g_Bolo[DM * DM];

// ============================= MMA helpers =================================
#define LDSM_X4(R, addr)                                                      \
    asm volatile("ldmatrix.sync.aligned.m8n8.x4.shared.b16 {%0,%1,%2,%3}, [%4];" \
        : "=r"((R)[0]), "=r"((R)[1]), "=r"((R)[2]), "=r"((R)[3]) : "r"(addr))

#define LDSM_X4_T(R, addr)                                                    \
    asm volatile("ldmatrix.sync.aligned.m8n8.x4.trans.shared.b16 {%0,%1,%2,%3}, [%4];" \
        : "=r"((R)[0]), "=r"((R)[1]), "=r"((R)[2]), "=r"((R)[3]) : "r"(addr))

#define MMA16816(C, A, b0, b1)                                                \
    asm volatile("mma.sync.aligned.m16n8k16.row.col.f32.bf16.bf16.f32 "       \
        "{%0,%1,%2,%3},{%4,%5,%6,%7},{%8,%9},{%0,%1,%2,%3};"                  \
        : "+f"((C)[0]), "+f"((C)[1]), "+f"((C)[2]), "+f"((C)[3])              \
        : "r"((A)[0]), "r"((A)[1]), "r"((A)[2]), "r"((A)[3]), "r"(b0), "r"(b1))

#define CP_ASYNC16(dst_u32, src_ptr)                                          \
    asm volatile("cp.async.cg.shared.global [%0], [%1], 16;"                  \
        :: "r"(dst_u32), "l"(src_ptr))
#define CP_COMMIT() asm volatile("cp.async.commit_group;" ::: "memory")
#define CP_WAIT0()  asm volatile("cp.async.wait_group 0;" ::: "memory")

__device__ __forceinline__ uint32_t smem_u32(const void* p) {
    uint32_t a;
    asm("{ .reg .u64 t; cvta.to.shared.u64 t, %1; cvt.u32.u64 %0, t; }"
        : "=r"(a) : "l"(p));
    return a;
}

// ============================ split helpers ================================
__device__ __forceinline__ void split_bf16(float x, __nv_bfloat16& hi, __nv_bfloat16& lo) {
    hi = __float2bfloat16_rn(x);
    lo = __float2bfloat16_rn(x - __bfloat162float(hi));
}
// split two floats -> packed bf16x2 hi word + lo word
__device__ __forceinline__ void split2(float a, float b, uint32_t& hi, uint32_t& lo) {
    __nv_bfloat162 h2, l2;
    split_bf16(a, h2.x, l2.x);
    split_bf16(b, h2.y, l2.y);
    hi = *reinterpret_cast<uint32_t*>(&h2);
    lo = *reinterpret_cast<uint32_t*>(&l2);
}

// ========================= conversion kernels ==============================
__global__ __launch_bounds__(256) void conv_x(const float* __restrict__ X,
                                              __nv_bfloat16* __restrict__ Ahi,
                                              __nv_bfloat16* __restrict__ Alo)
{
    const int idx = blockIdx.x * 256 + threadIdx.x;
    const int m  = idx >> 8;
    const int c  = (idx & 255) * 4;
    float4 v = *(const float4*)(X + m * DM + c);
    uint32_t h01, l01, h23, l23;
    split2(v.x, v.y, h01, l01);
    split2(v.z, v.w, h23, l23);
    *(uint32_t*)(Ahi + (size_t)m * DM + c)     = h01;
    *(uint32_t*)(Ahi + (size_t)m * DM + c + 2) = h23;
    *(uint32_t*)(Alo + (size_t)m * DM + c)     = l01;
    *(uint32_t*)(Alo + (size_t)m * DM + c + 2) = l23;
}

__global__ __launch_bounds__(256) void conv_w(const float* __restrict__ W,
                                              __nv_bfloat16* __restrict__ Bhi,
                                              __nv_bfloat16* __restrict__ Blo,
                                              int Nn)
{
    __shared__ float t[32][33];
    const int tx = threadIdx.x, ty = threadIdx.y;
    const int n0 = blockIdx.x * 32, k0 = blockIdx.y * 32;
#pragma unroll
    for (int i = 0; i < 32; i += 8)
        t[ty + i][tx] = W[(size_t)(k0 + ty + i) * Nn + n0 + tx];
    __syncthreads();
#pragma unroll
    for (int i = 0; i < 32; i += 8) {
        const int n = n0 + ty + i;
        const float v = t[tx][ty + i];
        __nv_bfloat16 hi, lo;
        split_bf16(v, hi, lo);
        Bhi[(size_t)n * DM + k0 + tx] = hi;
        Blo[(size_t)n * DM + k0 + tx] = lo;
    }
}

// ======================= HMMA bf16 GEMM (R13 core) =========================
constexpr int PIT   = 80;
constexpr int NCH   = DM / 32;           // 32 chunks
constexpr int TILE  = 128 * PIT;         // 10240 B
constexpr int OFF_ALO = TILE;
constexpr int OFF_BHI = 2 * TILE;
constexpr int OFF_BLO = 3 * TILE;
constexpr int STG   = 4 * TILE;          // 40960 B per stage
constexpr int TG_SMEM = 2 * STG;         // 81920 B

template <int EPI>
__global__ __launch_bounds__(256, 2) void tgemm(const __nv_bfloat16* __restrict__ Ahi,
                                                const __nv_bfloat16* __restrict__ Alo,
                                                const __nv_bfloat16* __restrict__ Bhi,
                                                const __nv_bfloat16* __restrict__ Blo,
                                                const float* __restrict__ bias,
                                                float* __restrict__ Cout)
{
    extern __shared__ __align__(16) char smem[];
    const uint32_t sbase = smem_u32(smem);

    const int tid  = threadIdx.x;
    const int wid  = tid >> 5;
    const int lane = tid & 31;
    const int wm   = wid >> 1;
    const int wn   = wid & 1;
    const int n0   = blockIdx.x * 128;
    const int m0   = blockIdx.y * 128;

    const int ldRow = tid >> 1;
    const int ldC   = (tid & 1) * 32;
    const char* gAh = (const char*)(Ahi + (size_t)(m0 + ldRow) * DM);
    const char* gAl = (const char*)(Alo + (size_t)(m0 + ldRow) * DM);
    const char* gBh = (const char*)(Bhi + (size_t)(n0 + ldRow) * DM);
    const char* gBl = (const char*)(Blo + (size_t)(n0 + ldRow) * DM);
    const uint32_t rowOff = ldRow * PIT + ldC;

    const int aOff0 = (wm * 32 +      (lane & 15)) * PIT + (lane >> 4) * 16;
    const int aOff1 = (wm * 32 + 16 + (lane & 15)) * PIT + (lane >> 4) * 16;
    const int bRow = wn * 64 + (lane & 7) + ((lane >> 4) << 3);
    const int bCol = ((lane >> 3) & 1) * 16;
    int bOff[4];
#pragma unroll
    for (int bt = 0; bt < 4; bt++)
        bOff[bt] = (bRow + bt * 16) * PIT + bCol;

    float c[2][8][4];
#pragma unroll
    for (int mt = 0; mt < 2; mt++)
#pragma unroll
        for (int nt = 0; nt < 8; nt++)
#pragma unroll
            for (int r = 0; r < 4; r++) c[mt][nt][r] = 0.f;

    auto issue_stage = [&](int ch, int s) {
        const uint32_t base = sbase + s * STG;
        const int kb = ch * 64;
        CP_ASYNC16(base + rowOff,                 gAh + kb + ldC);
        CP_ASYNC16(base + rowOff + 16,            gAh + kb + ldC + 16);
        CP_ASYNC16(base + OFF_ALO + rowOff,       gAl + kb + ldC);
        CP_ASYNC16(base + OFF_ALO + rowOff + 16,  gAl + kb + ldC + 16);
        CP_ASYNC16(base + OFF_BHI + rowOff,       gBh + kb + ldC);
        CP_ASYNC16(base + OFF_BHI + rowOff + 16,  gBh + kb + ldC + 16);
        CP_ASYNC16(base + OFF_BLO + rowOff,       gBl + kb + ldC);
        CP_ASYNC16(base + OFF_BLO + rowOff + 16,  gBl + kb + ldC + 16);
        CP_COMMIT();
    };

    issue_stage(0, 0);

    int s = 0;
    for (int ch = 0; ch < NCH; ch++) {
        CP_WAIT0();
        __syncthreads();
        if (ch + 1 < NCH) issue_stage(ch + 1, s ^ 1);

        const uint32_t sb = sbase + s * STG;
#pragma unroll
        for (int ks = 0; ks < 2; ks++) {
            const int ko = ks * 32;
            uint32_t ah[2][4], bh[4][4];
            LDSM_X4(ah[0], sb + aOff0 + ko);
            LDSM_X4(ah[1], sb + aOff1 + ko);
#pragma unroll
            for (int bt = 0; bt < 4; bt++)
                LDSM_X4(bh[bt], sb + OFF_BHI + bOff[bt] + ko);
#pragma unroll
            for (int mt = 0; mt < 2; mt++)
#pragma unroll
                for (int nt = 0; nt < 8; nt++)
                    MMA16816(c[mt][nt], ah[mt],
                             bh[nt >> 1][(nt & 1) * 2 + 0],
                             bh[nt >> 1][(nt & 1) * 2 + 1]);
            {
                uint32_t al[2][4];
                LDSM_X4(al[0], sb + OFF_ALO + aOff0 + ko);
                LDSM_X4(al[1], sb + OFF_ALO + aOff1 + ko);
#pragma unroll
                for (int mt = 0; mt < 2; mt++)
#pragma unroll
                    for (int nt = 0; nt < 8; nt++)
                        MMA16816(c[mt][nt], al[mt],
                                 bh[nt >> 1][(nt & 1) * 2 + 0],
                                 bh[nt >> 1][(nt & 1) * 2 + 1]);
            }
            {
                uint32_t bl[4][4];
#pragma unroll
                for (int bt = 0; bt < 4; bt++)
                    LDSM_X4(bl[bt], sb + OFF_BLO + bOff[bt] + ko);
#pragma unroll
                for (int mt = 0; mt < 2; mt++)
#pragma unroll
                    for (int nt = 0; nt < 8; nt++)
                        MMA16816(c[mt][nt], ah[mt],
                                 bl[nt >> 1][(nt & 1) * 2 + 0],
                                 bl[nt >> 1][(nt & 1) * 2 + 1]);
            }
        }
        s ^= 1;
    }

    // ---- epilogue ----
    const int g  = lane >> 2;
    const int tg = lane & 3;
#pragma unroll
    for (int mt = 0; mt < 2; mt++) {
#pragma unroll
        for (int half = 0; half < 2; half++) {
            const int m = m0 + wm * 32 + mt * 16 + g + half * 8;
            if (EPI == 0) {
                const int which = n0 >> 10;        // uniform per CTA
                __nv_bfloat16* dh = (which == 0) ? g_Qhi : (which == 1) ? g_Khi : g_Vhi;
                __nv_bfloat16* dl = (which == 0) ? g_Qlo : (which == 1) ? g_Klo : g_Vlo;
                const float scl = (which == 0) ? 0.125f : 1.0f;  // fold 1/sqrt(hd) into Q
                const int bb = m >> 11;
                const int ss = m & (SS - 1);
#pragma unroll
                for (int nt = 0; nt < 8; nt++) {
                    const int n = n0 + wn * 64 + nt * 8 + tg * 2;
                    const int hh = (n & (DM - 1)) >> 6;
                    const int d0 = n & 63;
                    const float vx = (c[mt][nt][half * 2 + 0] + bias[n + 0]) * scl;
                    const float vy = (c[mt][nt][half * 2 + 1] + bias[n + 1]) * scl;
                    uint32_t hi, lo;
                    split2(vx, vy, hi, lo);
                    const size_t off = ((size_t)(bb * NH + hh) * SS + ss) * HDm + d0;
                    *(uint32_t*)(dh + off) = hi;
                    *(uint32_t*)(dl + off) = lo;
                }
            } else {
#pragma unroll
                for (int nt = 0; nt < 8; nt++) {
                    const int n = n0 + wn * 64 + nt * 8 + tg * 2;
                    float2 v;
                    v.x = c[mt][nt][half * 2 + 0] + bias[n + 0];
                    v.y = c[mt][nt][half * 2 + 1] + bias[n + 1];
                    *(float2*)(Cout + (size_t)m * DM + n) = v;
                }
            }
        }
    }
}

// ===================== HMMA flash attention ================================
// CTA: 64 queries x (head, batch). 4 warps, 16 queries each.
// S = Qhi·Khi + Qlo·Khi + Qhi·Klo  (Q pre-scaled by 1/8)
// P (register-resident) split hi/lo; O += Phi·Vhi + Plo·Vhi + Phi·Vlo.
// K/V hi/lo tiles double-buffered via cp.async; V transposed via ldmatrix.trans.
constexpr int APQ   = 144;                 // smem row pitch (128B data + 16 pad)
constexpr int AQH   = 0;
constexpr int AQL   = 64 * APQ;            // 9216
constexpr int ASTG0 = 2 * 64 * APQ;        // 18432 (after Q region)
constexpr int A_KH  = 0;
constexpr int A_KL  = 64 * APQ;
constexpr int A_VH  = 2 * 64 * APQ;
constexpr int A_VL  = 3 * 64 * APQ;
constexpr int ASTG  = 4 * 64 * APQ;        // 36864 per stage
constexpr int ATTN_SMEM = ASTG0 + 2 * ASTG;  // 92160

__global__ __launch_bounds__(128) void attn_mma()
{
    extern __shared__ __align__(16) char sm[];
    const uint32_t sb = smem_u32(sm);
    const int tid  = threadIdx.x;
    const int w    = tid >> 5;
    const int lane = tid & 31;
    const int g    = lane >> 2;
    const int tg   = lane & 3;
    const int q0   = blockIdx.x * 64;
    const int h    = blockIdx.y;
    const int b    = blockIdx.z;

    const size_t hoff = (size_t)(b * NH + h) * SS * HDm;   // elements
    const char* Kh = (const char*)(g_Khi + hoff);
    const char* Kl = (const char*)(g_Klo + hoff);
    const char* Vh = (const char*)(g_Vhi + hoff);
    const char* Vl = (const char*)(g_Vlo + hoff);

    // copy one 64x128B tile into pitched smem
    auto cp_tile = [&](uint32_t dst, const char* src) {
#pragma unroll
        for (int i = 0; i < 4; i++) {
            const int c  = tid + i * 128;
            const int r  = c >> 3;
            const int cc = (c & 7) * 16;
            CP_ASYNC16(dst + r * APQ + cc, src + r * 128 + cc);
        }
    };
    auto issue_kv = [&](int s, int kb) {
        const uint32_t base = sb + ASTG0 + s * ASTG;
        const size_t boff = (size_t)kb * 8192;    // 64 keys * 128B
        cp_tile(base + A_KH, Kh + boff);
        cp_tile(base + A_KL, Kl + boff);
        cp_tile(base + A_VH, Vh + boff);
        cp_tile(base + A_VL, Vl + boff);
        CP_COMMIT();
    };

    const int kb_start = (q0 >= WIN) ? ((q0 - (WIN - 1)) >> 6) : 0;
    const int kb_end   = q0 >> 6;

    // prologue: Q tiles + first KV stage in one group
    cp_tile(sb + AQH, (const char*)(g_Qhi + hoff) + (size_t)q0 * 128);
    cp_tile(sb + AQL, (const char*)(g_Qlo + hoff) + (size_t)q0 * 128);
    issue_kv(0, kb_start);
    CP_WAIT0();
    __syncthreads();

    // Q fragments (register-resident, whole mainloop)
    uint32_t qh[4][4], ql[4][4];
    const uint32_t qoff = (uint32_t)((w * 16 + (lane & 15)) * APQ + (lane >> 4) * 16);
#pragma unroll
    for (int ks = 0; ks < 4; ks++) {
        LDSM_X4(qh[ks], sb + AQH + qoff + ks * 32);
        LDSM_X4(ql[ks], sb + AQL + qoff + ks * 32);
    }

    float o[8][4];
#pragma unroll
    for (int nd = 0; nd < 8; nd++)
#pragma unroll
        for (int r = 0; r < 4; r++) o[nd][r] = 0.f;
    float m0 = -1e30f, m1 = -1e30f, l0 = 0.f, l1 = 0.f;

    const uint32_t kRowOff = (uint32_t)(((lane & 7) + ((lane >> 4) << 3)) * APQ
                                        + ((lane >> 3) & 1) * 16);
    const uint32_t vRowOff = (uint32_t)(((lane & 7) + (((lane >> 3) & 1) << 3)) * APQ
                                        + (lane >> 4) * 16);

    const int r0 = q0 + w * 16 + g;
    const int r1 = r0 + 8;

    int s = 0;
    for (int kb = kb_start; kb <= kb_end; kb++) {
        if (kb < kb_end) issue_kv(s ^ 1, kb + 1);   // overlaps compute below
        const uint32_t stg = sb + ASTG0 + s * ASTG;

        // ---- S = Q K^T (3 products) ----
        float sc[8][4];
#pragma unroll
        for (int nt = 0; nt < 8; nt++)
#pragma unroll
            for (int r = 0; r < 4; r++) sc[nt][r] = 0.f;

#pragma unroll
        for (int ks = 0; ks < 4; ks++) {
            const uint32_t ko = ks * 32;
            uint32_t kh4[4][4];
#pragma unroll
            for (int kg = 0; kg < 4; kg++)
                LDSM_X4(kh4[kg], stg + A_KH + kg * (16 * APQ) + kRowOff + ko);
#pragma unroll
            for (int kg = 0; kg < 4; kg++) {
                MMA16816(sc[kg * 2 + 0], qh[ks], kh4[kg][0], kh4[kg][1]);
                MMA16816(sc[kg * 2 + 1], qh[ks], kh4[kg][2], kh4[kg][3]);
                MMA16816(sc[kg * 2 + 0], ql[ks], kh4[kg][0], kh4[kg][1]);
                MMA16816(sc[kg * 2 + 1], ql[ks], kh4[kg][2], kh4[kg][3]);
            }
#pragma unroll
            for (int kg = 0; kg < 4; kg++) {
                uint32_t kl4[4];
                LDSM_X4(kl4, stg + A_KL + kg * (16 * APQ) + kRowOff + ko);
                MMA16816(sc[kg * 2 + 0], qh[ks], kl4[0], kl4[1]);
                MMA16816(sc[kg * 2 + 1], qh[ks], kl4[2], kl4[3]);
            }
        }

        // ---- mask + online softmax ----
        const int diff = q0 - kb * 64;
        const bool full = (diff >= 63) && (diff + 63 < WIN);
        if (!full) {
#pragma unroll
            for (int nt = 0; nt < 8; nt++) {
#pragma unroll
                for (int cc = 0; cc < 2; cc++) {
                    const int key = kb * 64 + nt * 8 + 2 * tg + cc;
                    const int d0 = r0 - key;
                    const int d1 = r1 - key;
                    if (d0 < 0 || d0 >= WIN) sc[nt][cc]     = -1e30f;
                    if (d1 < 0 || d1 >= WIN) sc[nt][2 + cc] = -1e30f;
                }
            }
        }
        float mx0 = -1e30f, mx1 = -1e30f;
#pragma unroll
        for (int nt = 0; nt < 8; nt++) {
            mx0 = fmaxf(mx0, fmaxf(sc[nt][0], sc[nt][1]));
            mx1 = fmaxf(mx1, fmaxf(sc[nt][2], sc[nt][3]));
        }
        mx0 = fmaxf(mx0, __shfl_xor_sync(0xffffffffu, mx0, 1));
        mx0 = fmaxf(mx0, __shfl_xor_sync(0xffffffffu, mx0, 2));
        mx1 = fmaxf(mx1, __shfl_xor_sync(0xffffffffu, mx1, 1));
        mx1 = fmaxf(mx1, __shfl_xor_sync(0xffffffffu, mx1, 2));

        const float mn0 = fmaxf(m0, mx0);
        const float mn1 = fmaxf(m1, mx1);
        const float c0 = __expf(m0 - mn0);
        const float c1 = __expf(m1 - mn1);

        float ps0 = 0.f, ps1 = 0.f;
#pragma unroll
        for (int nt = 0; nt < 8; nt++) {
            // guard: fully-masked rows (mn == -1e30) must yield p = 0
            sc[nt][0] = (sc[nt][0] > -1e29f) ? __expf(sc[nt][0] - mn0) : 0.f;
            sc[nt][1] = (sc[nt][1] > -1e29f) ? __expf(sc[nt][1] - mn0) : 0.f;
            sc[nt][2] = (sc[nt][2] > -1e29f) ? __expf(sc[nt][2] - mn1) : 0.f;
            sc[nt][3] = (sc[nt][3] > -1e29f) ? __expf(sc[nt][3] - mn1) : 0.f;
            ps0 += sc[nt][0] + sc[nt][1];
            ps1 += sc[nt][2] + sc[nt][3];
        }
        ps0 += __shfl_xor_sync(0xffffffffu, ps0, 1);
        ps0 += __shfl_xor_sync(0xffffffffu, ps0, 2);
        ps1 += __shfl_xor_sync(0xffffffffu, ps1, 1);
        ps1 += __shfl_xor_sync(0xffffffffu, ps1, 2);

        l0 = l0 * c0 + ps0;  m0 = mn0;
        l1 = l1 * c1 + ps1;  m1 = mn1;
#pragma unroll
        for (int nd = 0; nd < 8; nd++) {
            o[nd][0] *= c0; o[nd][1] *= c0;
            o[nd][2] *= c1; o[nd][3] *= c1;
        }

        // ---- O += P V (3 products), P repacked from S accum frags ----
#pragma unroll
        for (int j = 0; j < 4; j++) {
            uint32_t ph[4], pl[4];
            split2(sc[2*j][0],   sc[2*j][1],   ph[0], pl[0]);
            split2(sc[2*j][2],   sc[2*j][3],   ph[1], pl[1]);
            split2(sc[2*j+1][0], sc[2*j+1][1], ph[2], pl[2]);
            split2(sc[2*j+1][2], sc[2*j+1][3], ph[3], pl[3]);
#pragma unroll
            for (int dg = 0; dg < 4; dg++) {
                uint32_t vh4[4], vl4[4];
                LDSM_X4_T(vh4, stg + A_VH + j * (16 * APQ) + vRowOff + dg * 32);
                LDSM_X4_T(vl4, stg + A_VL + j * (16 * APQ) + vRowOff + dg * 32);
                MMA16816(o[dg * 2 + 0], ph, vh4[0], vh4[1]);
                MMA16816(o[dg * 2 + 1], ph, vh4[2], vh4[3]);
                MMA16816(o[dg * 2 + 0], pl, vh4[0], vh4[1]);
                MMA16816(o[dg * 2 + 1], pl, vh4[2], vh4[3]);
                MMA16816(o[dg * 2 + 0], ph, vl4[0], vl4[1]);
                MMA16816(o[dg * 2 + 1], ph, vl4[2], vl4[3]);
            }
        }

        if (kb < kb_end) { CP_WAIT0(); __syncthreads(); }
        s ^= 1;
    }

    // ---- normalize + store split-bf16 AO ----
    const float i0 = 1.f / l0;
    const float i1 = 1.f / l1;
#pragma unroll
    for (int nd = 0; nd < 8; nd++) {
        const size_t base0 = (size_t)(b * SS + r0) * DM + h * 64 + nd * 8 + 2 * tg;
        const size_t base1 = base0 + (size_t)8 * DM;
        uint32_t hi, lo;
        split2(o[nd][0] * i0, o[nd][1] * i0, hi, lo);
        *(uint32_t*)(g_AOhi + base0) = hi;
        *(uint32_t*)(g_AOlo + base0) = lo;
        split2(o[nd][2] * i1, o[nd][3] * i1, hi, lo);
        *(uint32_t*)(g_AOhi + base1) = hi;
        *(uint32_t*)(g_AOlo + base1) = lo;
    }
}

// ---------------------------------------------------------------------------
extern "C" void kernel_launch(void* const* d_in, const int* in_sizes, int n_in,
                              void* d_out, int out_size)
{
    const float* x     = (const float*)d_in[0];
    const float* qkvw  = (const float*)d_in[1];
    const float* qkvb  = (const float*)d_in[2];
    const float* outw  = (const float*)d_in[3];
    const float* outb  = (const float*)d_in[4];
    float* out = (float*)d_out;

    cudaFuncSetAttribute(attn_mma, cudaFuncAttributeMaxDynamicSharedMemorySize,
                         ATTN_SMEM);
    cudaFuncSetAttribute(tgemm<0>, cudaFuncAttributeMaxDynamicSharedMemorySize, TG_SMEM);
    cudaFuncSetAttribute(tgemm<1>, cudaFuncAttributeMaxDynamicSharedMemorySize, TG_SMEM);

    __nv_bfloat16 *Ahi, *Alo, *AOhi, *AOlo, *Bqhi, *Bqlo, *Bohi, *Bolo;
    cudaGetSymbolAddress((void**)&Ahi,  g_Ahi);
    cudaGetSymbolAddress((void**)&Alo,  g_Alo);
    cudaGetSymbolAddress((void**)&AOhi, g_AOhi);
    cudaGetSymbolAddress((void**)&AOlo, g_AOlo);
    cudaGetSymbolAddress((void**)&Bqhi, g_Bqhi);
    cudaGetSymbolAddress((void**)&Bqlo, g_Bqlo);
    cudaGetSymbolAddress((void**)&Bohi, g_Bohi);
    cudaGetSymbolAddress((void**)&Bolo, g_Bolo);

    // 0) split-precision conversions
    conv_x<<<MT * DM / 1024, 256>>>(x, Ahi, Alo);
    conv_w<<<dim3(ND3 / 32, DM / 32), dim3(32, 8)>>>(qkvw, Bqhi, Bqlo, ND3);
    conv_w<<<dim3(DM  / 32, DM / 32), dim3(32, 8)>>>(outw, Bohi, Bolo, DM);

    // 1) QKV projection -> pre-split bf16 Q/K/V (Q scaled by 1/8)
    tgemm<0><<<dim3(ND3 / 128, MT / 128), 256, TG_SMEM>>>(Ahi, Alo, Bqhi, Bqlo,
                                                          qkvb, nullptr);

    // 2) Windowed attention on HMMA, writes split-bf16 AO
    attn_mma<<<dim3(SS / 64, NH, BB), 128, ATTN_SMEM>>>();

    // 3) Output projection (bf16 HMMA 3-product)
    tgemm<1><<<dim3(DM / 128, MT / 128), 256, TG_SMEM>>>(AOhi, AOlo, Bohi, Bolo,
                                                         outb, out);
}